// round 13
// baseline (speedup 1.0000x reference)
#include <cuda_runtime.h>
#include <cuda_bf16.h>
#include <mma.h>
#include <math.h>
#include <stdint.h>

using namespace nvcuda;

#define BATCH 4
#define TLEN  2048
#define CDIM  2048
#define HS    64
#define NH    32
#define MTOT  (BATCH*TLEN)   /* 8192 */

/* ---------------- scratch (static device allocations; no cudaMalloc) ------- */
__device__ float g_X  [(size_t)MTOT*CDIM];
__device__ float g_XX1[(size_t)MTOT*128];
__device__ float g_MIX[4][(size_t)MTOT*CDIM];
__device__ float g_XW1[(size_t)MTOT*32];
__device__ float g_XW [(size_t)MTOT*CDIM];
__device__ float g_T1 [(size_t)MTOT*128];
__device__ float g_DEC[(size_t)MTOT*CDIM];
__device__ float g_R  [(size_t)MTOT*CDIM];
__device__ float g_K  [(size_t)MTOT*CDIM];
__device__ float g_V  [(size_t)MTOT*CDIM];
__device__ float g_V2 [(size_t)MTOT*CDIM];
__device__ float g_Y  [(size_t)MTOT*CDIM];
__device__ float g_YN [(size_t)MTOT*CDIM];

/* ================= bf16-split WMMA GEMM (NT), fp32-direct loaders ==========
   C[m,n] = sum_k A[m,k]*B[n,k] with A,B fp32 in gmem; the loader converts
   to bf16 hi/lo pairs on the fly (Sterbenz-exact residual in fp32) while
   storing to shared. Accumulate AH*BH + AH*BL + AL*BH in fp32 (lo*lo
   dropped). Block 128x128, 8 warps (2x4), warp tile 64x32, K-chunk 32,
   register prefetch of chunk c+1's fp32 data under chunk c's HMMA phase. */
#define WLD 40   /* smem row pitch in bf16 */

__device__ __forceinline__ void st_hilo(__nv_bfloat16* H, __nv_bfloat16* L, float4 v)
{
    __nv_bfloat16 h0 = __float2bfloat16(v.x), h1 = __float2bfloat16(v.y);
    __nv_bfloat16 h2 = __float2bfloat16(v.z), h3 = __float2bfloat16(v.w);
    __nv_bfloat162 hA; hA.x = h0; hA.y = h1;
    __nv_bfloat162 hB; hB.x = h2; hB.y = h3;
    __nv_bfloat162 lA; lA.x = __float2bfloat16(v.x - __bfloat162float(h0));
                       lA.y = __float2bfloat16(v.y - __bfloat162float(h1));
    __nv_bfloat162 lB; lB.x = __float2bfloat16(v.z - __bfloat162float(h2));
                       lB.y = __float2bfloat16(v.w - __bfloat162float(h3));
    ((__nv_bfloat162*)H)[0] = hA;  ((__nv_bfloat162*)H)[1] = hB;
    ((__nv_bfloat162*)L)[0] = lA;  ((__nv_bfloat162*)L)[1] = lB;
}

__global__ __launch_bounds__(256)
void gemm_wmma3(const float* __restrict__ A, const float* __restrict__ B,
                float* __restrict__ C, int M, int N, int K)
{
    __shared__ __nv_bfloat16 AsH[128][WLD];
    __shared__ __nv_bfloat16 AsL[128][WLD];
    __shared__ __nv_bfloat16 BsH[128][WLD];
    __shared__ __nv_bfloat16 BsL[128][WLD];

    const int tid = threadIdx.x;
    const int wid = tid >> 5;
    const int wm = wid & 1;        /* 0..1  -> 64-row slab  */
    const int wn = wid >> 1;       /* 0..3  -> 32-col slab  */
    const int bm = blockIdx.y * 128;
    const int bn = blockIdx.x * 128;

    wmma::fragment<wmma::accumulator, 16, 16, 16, float> acc[4][2];
#pragma unroll
    for (int i = 0; i < 4; i++)
#pragma unroll
        for (int j = 0; j < 2; j++) wmma::fill_fragment(acc[i][j], 0.f);

    /* loader mapping: i = tid + u*256 -> row = i>>3, col4 = (i&7)*4 floats */
    int lrow[4], lc4[4];
#pragma unroll
    for (int u = 0; u < 4; u++) {
        int i = tid + (u << 8);
        lrow[u] = i >> 3;
        lc4[u]  = (i & 7) << 2;
    }

    float4 pA[4], pB[4];
#pragma unroll
    for (int u = 0; u < 4; u++) {
        pA[u] = *(const float4*)(A + (size_t)(bm + lrow[u]) * K + lc4[u]);
        pB[u] = *(const float4*)(B + (size_t)(bn + lrow[u]) * K + lc4[u]);
    }

    const int nchunks = K >> 5;
    for (int c = 0; c < nchunks; c++) {
        /* convert + store prefetched chunk c to smem */
#pragma unroll
        for (int u = 0; u < 4; u++) {
            st_hilo(&AsH[lrow[u]][lc4[u]], &AsL[lrow[u]][lc4[u]], pA[u]);
            st_hilo(&BsH[lrow[u]][lc4[u]], &BsL[lrow[u]][lc4[u]], pB[u]);
        }
        __syncthreads();

        /* issue chunk c+1's fp32 loads; latency hides under wmma phase */
        if (c + 1 < nchunks) {
            const int k0 = (c + 1) << 5;
#pragma unroll
            for (int u = 0; u < 4; u++) {
                pA[u] = *(const float4*)(A + (size_t)(bm + lrow[u]) * K + k0 + lc4[u]);
                pB[u] = *(const float4*)(B + (size_t)(bn + lrow[u]) * K + k0 + lc4[u]);
            }
        }

#pragma unroll
        for (int ks = 0; ks < 2; ks++) {
            wmma::fragment<wmma::matrix_b, 16, 16, 16, __nv_bfloat16, wmma::col_major> bh[2], bl[2];
#pragma unroll
            for (int j = 0; j < 2; j++) {
                wmma::load_matrix_sync(bh[j], &BsH[wn*32 + j*16][ks*16], WLD);
                wmma::load_matrix_sync(bl[j], &BsL[wn*32 + j*16][ks*16], WLD);
            }
#pragma unroll
            for (int i = 0; i < 4; i++) {
                wmma::fragment<wmma::matrix_a, 16, 16, 16, __nv_bfloat16, wmma::row_major> ah, al;
                wmma::load_matrix_sync(ah, &AsH[wm*64 + i*16][ks*16], WLD);
                wmma::load_matrix_sync(al, &AsL[wm*64 + i*16][ks*16], WLD);
#pragma unroll
                for (int j = 0; j < 2; j++) {
                    wmma::mma_sync(acc[i][j], ah, bh[j], acc[i][j]);
                    wmma::mma_sync(acc[i][j], ah, bl[j], acc[i][j]);
                    wmma::mma_sync(acc[i][j], al, bh[j], acc[i][j]);
                }
            }
        }
        __syncthreads();
    }

#pragma unroll
    for (int i = 0; i < 4; i++)
#pragma unroll
        for (int j = 0; j < 2; j++)
            wmma::store_matrix_sync(&C[(size_t)(bm + wm*64 + i*16) * N + bn + wn*32 + j*16],
                                    acc[i][j], N, wmma::mem_row_major);
}

/* ---------------- generic NN GEMM: C[m,n] = f(sum_k A[m,lda..]*B[k,n]) ------
   epi: 0=none, 1=tanh, 2=exp(-exp(bias[n]+acc)),
        3=XW fusion: C = X + (Xprev - X) * (tmw[n] + acc)                  */
__global__ __launch_bounds__(256, 2)
void gemm_nn(const float* __restrict__ A, int lda, int aoff,
             const float* __restrict__ B, int ldb,
             float* __restrict__ C, int ldc,
             int M, int N, int K, int epi, const float* __restrict__ bias,
             const float* __restrict__ Xf, const float* __restrict__ shf,
             const float* __restrict__ tw)
{
    __shared__ float As[64][36];
    __shared__ float Bs[32][128];
    const int tid = threadIdx.x;
    const int bm = blockIdx.y * 64;
    const int bn = blockIdx.x * 128;
    const int cx = tid & 31;
    const int rg = tid >> 5;

    float4 acc[8];
#pragma unroll
    for (int r = 0; r < 8; r++) acc[r] = make_float4(0.f,0.f,0.f,0.f);

    for (int k0 = 0; k0 < K; k0 += 32) {
#pragma unroll
        for (int u = 0; u < 2; u++) {
            int i = tid + 256*u;
            int r = i >> 3, kq = (i & 7) << 2;
            float4 v = *(const float4*)&A[(size_t)(bm + r) * lda + aoff + k0 + kq];
            *(float4*)&As[r][kq] = v;
        }
#pragma unroll
        for (int u = 0; u < 4; u++) {
            int i = tid + 256*u;
            int kr = i >> 5, nq = (i & 31) << 2;
            float4 v = make_float4(0.f,0.f,0.f,0.f);
            if (bn + nq < N)
                v = *(const float4*)&B[(size_t)(k0 + kr) * ldb + bn + nq];
            *(float4*)&Bs[kr][nq] = v;
        }
        __syncthreads();
#pragma unroll 8
        for (int k = 0; k < 32; k++) {
            float4 bv = *(const float4*)&Bs[k][cx << 2];
#pragma unroll
            for (int r = 0; r < 8; r++) {
                float a = As[rg*8 + r][k];
                acc[r].x = fmaf(a, bv.x, acc[r].x);
                acc[r].y = fmaf(a, bv.y, acc[r].y);
                acc[r].z = fmaf(a, bv.z, acc[r].z);
                acc[r].w = fmaf(a, bv.w, acc[r].w);
            }
        }
        __syncthreads();
    }
    const int n = bn + (cx << 2);
    if (n < N) {
#pragma unroll
        for (int r = 0; r < 8; r++) {
            float4 o = acc[r];
            if (epi == 1) {
                o.x = tanhf(o.x); o.y = tanhf(o.y); o.z = tanhf(o.z); o.w = tanhf(o.w);
            } else if (epi == 2) {
                o.x = expf(-expf(bias[n+0] + o.x));
                o.y = expf(-expf(bias[n+1] + o.y));
                o.z = expf(-expf(bias[n+2] + o.z));
                o.w = expf(-expf(bias[n+3] + o.w));
            } else if (epi == 3) {
                const int m = bm + rg*8 + r;
                const int t = m & (TLEN-1), b = m >> 11;
                float4 x  = *(const float4*)&Xf[(size_t)m * CDIM + n];
                float4 xp = (t == 0)
                    ? *(const float4*)&shf[(size_t)b * CDIM + n]
                    : *(const float4*)&Xf[(size_t)(m-1) * CDIM + n];
                float4 w  = *(const float4*)&tw[n];
                o.x = x.x + (xp.x - x.x) * (w.x + o.x);
                o.y = x.y + (xp.y - x.y) * (w.y + o.y);
                o.z = x.z + (xp.z - x.z) * (w.z + o.z);
                o.w = x.w + (xp.w - x.w) * (w.w + o.w);
            }
            *(float4*)&C[(size_t)(bm + rg*8 + r) * ldc + n] = o;
        }
    }
}

/* ---------------- elementwise: r, k, v, v2 --------------------------------- */
__global__ void ew_rkvv_kernel(const float* __restrict__ X, const float* __restrict__ shiftst,
    const float* __restrict__ M0, const float* __restrict__ M1,
    const float* __restrict__ M2, const float* __restrict__ M3,
    const float* __restrict__ DEC,
    const float* __restrict__ tmr, const float* __restrict__ tmk,
    const float* __restrict__ tmv, const float* __restrict__ tmv2,
    const float* __restrict__ trec, const float* __restrict__ tkey,
    float* __restrict__ R, float* __restrict__ K,
    float* __restrict__ V, float* __restrict__ V2)
{
    int i4 = blockIdx.x * 256 + threadIdx.x;
    int m = i4 >> 9, c4 = i4 & 511;
    int t = m & (TLEN-1), b = m >> 11;
    const float4* X4 = (const float4*)X;
    float4 x  = X4[i4];
    float4 xp = (t == 0) ? ((const float4*)shiftst)[(b << 9) + c4] : X4[i4 - 512];
    float4 m0 = ((const float4*)M0)[i4];
    float4 m1 = ((const float4*)M1)[i4];
    float4 m2 = ((const float4*)M2)[i4];
    float4 m3 = ((const float4*)M3)[i4];
    float4 d  = ((const float4*)DEC)[i4];
    float4 cr = ((const float4*)tmr)[c4];
    float4 ck = ((const float4*)tmk)[c4];
    float4 cv = ((const float4*)tmv)[c4];
    float4 c2 = ((const float4*)tmv2)[c4];
    float4 rc = ((const float4*)trec)[c4];
    float4 kc = ((const float4*)tkey)[c4];
    float4 o_r, o_k, o_v, o_w;
#define RKVV_APPLY(f) do { \
    float dxv = xp.f - x.f; \
    o_r.f = (x.f + dxv*(cr.f + m0.f)) * rc.f; \
    o_k.f = (x.f + dxv*(ck.f + m1.f)) * kc.f * (1.f - d.f); \
    o_v.f =  x.f + dxv*(cv.f + m2.f); \
    o_w.f =  x.f + dxv*(c2.f + m3.f); \
} while(0)
    RKVV_APPLY(x); RKVV_APPLY(y); RKVV_APPLY(z); RKVV_APPLY(w);
#undef RKVV_APPLY
    ((float4*)R )[i4] = o_r;
    ((float4*)K )[i4] = o_k;
    ((float4*)V )[i4] = o_v;
    ((float4*)V2)[i4] = o_w;
}

/* ---------------- WKV sequential scan, 8-step groups -----------------------
   1 block per (b,h). tid = j*4 + iq: thread owns S[iq*16..iq*16+15][j] in
   registers. 8 time-steps are staged to shared per barrier pair (write all
   8 vectors -> sync -> 8 compute steps -> sync) cutting barrier count 4x.
   u == 0 in this model, so y uses the pre-update state.                  */
#define GSTEP 8
__global__ __launch_bounds__(256, 1)
void wkv_kernel(const float* __restrict__ Rp, const float* __restrict__ Kp,
                const float* __restrict__ Vp, const float* __restrict__ Dp,
                const float* __restrict__ S0, float* __restrict__ Y)
{
    const int bh = blockIdx.x;
    const int b = bh >> 5, h = bh & (NH-1);
    const int tid = threadIdx.x;
    const int j = tid >> 2, iq = tid & 3;

    float S[16];
    const float* s0p = S0 + (size_t)bh * HS * HS;
#pragma unroll
    for (int ii = 0; ii < 16; ii++) S[ii] = s0p[((iq << 4) + ii) * HS + j];

    __shared__ float sbuf[GSTEP][4][64];

    const int grp = tid >> 6, lane = tid & 63;
    const size_t base = ((size_t)b * TLEN) * CDIM + h * HS;
    const float* myp =
        ((grp == 0) ? Rp : (grp == 1) ? Kp : (grp == 2) ? Dp : Vp) + base + lane;

    float pre[GSTEP];
#pragma unroll
    for (int u = 0; u < GSTEP; u++) pre[u] = myp[(size_t)u * CDIM];

    const size_t ybase = base;
    for (int tc = 0; tc < TLEN; tc += GSTEP) {
#pragma unroll
        for (int u = 0; u < GSTEP; u++) sbuf[u][grp][lane] = pre[u];
        __syncthreads();
        if (tc + GSTEP < TLEN) {
#pragma unroll
            for (int u = 0; u < GSTEP; u++)
                pre[u] = myp[(size_t)(tc + GSTEP + u) * CDIM];
        }
#pragma unroll
        for (int u = 0; u < GSTEP; u++) {
            const float4* r4 = (const float4*)sbuf[u][0];
            const float4* k4 = (const float4*)sbuf[u][1];
            const float4* d4 = (const float4*)sbuf[u][2];
            const float vj = sbuf[u][3][j];
            float y = 0.f;
#pragma unroll
            for (int q = 0; q < 4; q++) {
                float4 rv = r4[iq*4 + q];
                y = fmaf(rv.x, S[q*4+0], y);
                y = fmaf(rv.y, S[q*4+1], y);
                y = fmaf(rv.z, S[q*4+2], y);
                y = fmaf(rv.w, S[q*4+3], y);
            }
#pragma unroll
            for (int q = 0; q < 4; q++) {
                float4 dv = d4[iq*4 + q];
                float4 kv = k4[iq*4 + q];
                S[q*4+0] = fmaf(dv.x, S[q*4+0], kv.x * vj);
                S[q*4+1] = fmaf(dv.y, S[q*4+1], kv.y * vj);
                S[q*4+2] = fmaf(dv.z, S[q*4+2], kv.z * vj);
                S[q*4+3] = fmaf(dv.w, S[q*4+3], kv.w * vj);
            }
            y += __shfl_xor_sync(0xffffffffu, y, 1);
            y += __shfl_xor_sync(0xffffffffu, y, 2);
            if (iq == 0) Y[ybase + (size_t)(tc + u) * CDIM + j] = y;
        }
        __syncthreads();
    }
}

/* ---------------- fused add + LayerNorm (fp32 out) ------------------------- */
__global__ void ln_kernel(const float* __restrict__ Y, const float* __restrict__ V2,
                          const float* __restrict__ gamma, const float* __restrict__ beta,
                          float* __restrict__ YN)
{
    const int m = blockIdx.x;
    const int tid = threadIdx.x;
    const float4* y4 = (const float4*)(Y  + (size_t)m * CDIM);
    const float4* v4 = (const float4*)(V2 + (size_t)m * CDIM);
    float4 vals[2];
    float s = 0.f, s2 = 0.f;
#pragma unroll
    for (int u = 0; u < 2; u++) {
        float4 a = y4[tid + u*256], b = v4[tid + u*256];
        float4 v = make_float4(a.x+b.x, a.y+b.y, a.z+b.z, a.w+b.w);
        vals[u] = v;
        s  += v.x + v.y + v.z + v.w;
        s2 += v.x*v.x + v.y*v.y + v.z*v.z + v.w*v.w;
    }
#pragma unroll
    for (int o = 16; o; o >>= 1) {
        s  += __shfl_xor_sync(0xffffffffu, s,  o);
        s2 += __shfl_xor_sync(0xffffffffu, s2, o);
    }
    __shared__ float sh[2][8];
    const int w = tid >> 5, l = tid & 31;
    if (l == 0) { sh[0][w] = s; sh[1][w] = s2; }
    __syncthreads();
    s = 0.f; s2 = 0.f;
#pragma unroll
    for (int i = 0; i < 8; i++) { s += sh[0][i]; s2 += sh[1][i]; }
    const float mu   = s  * (1.f / CDIM);
    const float var  = s2 * (1.f / CDIM) - mu * mu;
    const float rstd = rsqrtf(var + 1e-5f);
    const float4* g4 = (const float4*)gamma;
    const float4* b4 = (const float4*)beta;
    float4* o4 = (float4*)(YN + (size_t)m * CDIM);
#pragma unroll
    for (int u = 0; u < 2; u++) {
        int c4 = tid + u*256;
        float4 g = g4[c4], bb = b4[c4], v = vals[u];
        float4 o;
        o.x = (v.x - mu) * rstd * g.x + bb.x;
        o.y = (v.y - mu) * rstd * g.y + bb.y;
        o.z = (v.z - mu) * rstd * g.z + bb.z;
        o.w = (v.w - mu) * rstd * g.w + bb.w;
        o4[c4] = o;
    }
}

/* ---------------- launch --------------------------------------------------- */
extern "C" void kernel_launch(void* const* d_in, const int* in_sizes, int n_in,
                              void* d_out, int out_size)
{
    const float* x_in     = (const float*)d_in[0];
    const float* shiftst  = (const float*)d_in[1];
    const float* wkvstate = (const float*)d_in[2];
    const float* tmr      = (const float*)d_in[3];
    const float* tmk      = (const float*)d_in[4];
    const float* tmv      = (const float*)d_in[5];
    const float* tmv2     = (const float*)d_in[6];
    const float* maa_w1   = (const float*)d_in[7];
    const float* maa_w2   = (const float*)d_in[8];
    const float* tmw      = (const float*)d_in[9];
    const float* ww1      = (const float*)d_in[10];
    const float* ww2      = (const float*)d_in[11];
    const float* tdecay   = (const float*)d_in[12];
    const float* dw1      = (const float*)d_in[13];
    const float* dw2      = (const float*)d_in[14];
    /* d_in[15] = time_faaaa: unused (u == 0 in this model) */
    const float* trec     = (const float*)d_in[16];
    const float* tkey     = (const float*)d_in[17];
    const float* value_w  = (const float*)d_in[18];
    const float* output_w = (const float*)d_in[19];
    const float* gamma    = (const float*)d_in[20];
    const float* beta     = (const float*)d_in[21];
    float* out = (float*)d_out;

    float *pX, *pXX1, *pMIX, *pXW1, *pXW, *pT1, *pDEC, *pR, *pK, *pV, *pV2, *pY, *pYN;
    cudaGetSymbolAddress((void**)&pX,   g_X);
    cudaGetSymbolAddress((void**)&pXX1, g_XX1);
    cudaGetSymbolAddress((void**)&pMIX, g_MIX);
    cudaGetSymbolAddress((void**)&pXW1, g_XW1);
    cudaGetSymbolAddress((void**)&pXW,  g_XW);
    cudaGetSymbolAddress((void**)&pT1,  g_T1);
    cudaGetSymbolAddress((void**)&pDEC, g_DEC);
    cudaGetSymbolAddress((void**)&pR,   g_R);
    cudaGetSymbolAddress((void**)&pK,   g_K);
    cudaGetSymbolAddress((void**)&pV,   g_V);
    cudaGetSymbolAddress((void**)&pV2,  g_V2);
    cudaGetSymbolAddress((void**)&pY,   g_Y);
    cudaGetSymbolAddress((void**)&pYN,  g_YN);

    const size_t SZ = (size_t)MTOT * CDIM;
    const int EW_BLOCKS = (int)(SZ / 4 / 256);
    const float* NUL = (const float*)0;

    /* X = x_in @ value_w^T  (wmma bf16x3, fp32-direct loaders) */
    gemm_wmma3<<<dim3(CDIM/128, MTOT/128), 256>>>(x_in, value_w, pX, MTOT, CDIM, CDIM);

    /* XX1 = tanh(x_in @ maa_w1) */
    gemm_nn<<<dim3(1, MTOT/64), 256>>>(x_in, CDIM, 0, maa_w1, 128, pXX1, 128,
                                       MTOT, 128, CDIM, 1, NUL, NUL, NUL, NUL);
    /* MIX[f] = XX1[:, f*32:(f+1)*32] @ maa_w2[f] */
    for (int f = 0; f < 4; f++)
        gemm_nn<<<dim3(CDIM/128, MTOT/64), 256>>>(pXX1, 128, f*32,
                                                  maa_w2 + (size_t)f*32*CDIM, CDIM,
                                                  pMIX + (size_t)f*SZ, CDIM,
                                                  MTOT, CDIM, 32, 0, NUL, NUL, NUL, NUL);
    /* XW1 = tanh(X @ w_w1) */
    gemm_nn<<<dim3(1, MTOT/64), 256>>>(pX, CDIM, 0, ww1, 32, pXW1, 32,
                                       MTOT, 32, CDIM, 1, NUL, NUL, NUL, NUL);
    /* XW = X + dxprev*(time_maa_w + XW1 @ w_w2)  (fused epi=3) */
    gemm_nn<<<dim3(CDIM/128, MTOT/64), 256>>>(pXW1, 32, 0, ww2, CDIM, pXW, CDIM,
                                              MTOT, CDIM, 32, 3, NUL,
                                              pX, shiftst, tmw);
    /* T1 = tanh(XW @ decay_w1) */
    gemm_nn<<<dim3(1, MTOT/64), 256>>>(pXW, CDIM, 0, dw1, 128, pT1, 128,
                                       MTOT, 128, CDIM, 1, NUL, NUL, NUL, NUL);
    /* DEC = exp(-exp(time_decay + T1 @ decay_w2)) */
    gemm_nn<<<dim3(CDIM/128, MTOT/64), 256>>>(pT1, 128, 0, dw2, CDIM, pDEC, CDIM,
                                              MTOT, CDIM, 128, 2, tdecay, NUL, NUL, NUL);
    /* r, k, v, v2 */
    ew_rkvv_kernel<<<EW_BLOCKS, 256>>>(pX, shiftst,
                                       pMIX, pMIX + SZ, pMIX + 2*SZ, pMIX + 3*SZ,
                                       pDEC, tmr, tmk, tmv, tmv2, trec, tkey,
                                       pR, pK, pV, pV2);
    /* WKV scan (8-step groups) */
    wkv_kernel<<<BATCH*NH, 256>>>(pR, pK, pV, pDEC, wkvstate, pY);
    /* yn = LN(y + v2) (fp32) */
    ln_kernel<<<MTOT, 256>>>(pY, pV2, gamma, beta, pYN);
    /* out = yn @ output_w^T  (wmma bf16x3, fp32-direct loaders) */
    gemm_wmma3<<<dim3(CDIM/128, MTOT/128), 256>>>(pYN, output_w, out, MTOT, CDIM, CDIM);
}

// round 14
// speedup vs baseline: 1.0487x; 1.0487x over previous
#include <cuda_runtime.h>
#include <cuda_bf16.h>
#include <mma.h>
#include <math.h>
#include <stdint.h>

using namespace nvcuda;

#define BATCH 4
#define TLEN  2048
#define CDIM  2048
#define HS    64
#define NH    32
#define MTOT  (BATCH*TLEN)   /* 8192 */

/* ---------------- scratch (static device allocations; no cudaMalloc) ------- */
__device__ float g_X  [(size_t)MTOT*CDIM];
__device__ float g_XX1[(size_t)MTOT*128];
__device__ float g_MIX[4][(size_t)MTOT*CDIM];
__device__ float g_XW1[(size_t)MTOT*32];
__device__ float g_T1 [(size_t)MTOT*128];
__device__ float g_DEC[(size_t)MTOT*CDIM];
__device__ float g_R  [(size_t)MTOT*CDIM];
__device__ float g_K  [(size_t)MTOT*CDIM];
__device__ float g_V  [(size_t)MTOT*CDIM];
__device__ float g_V2 [(size_t)MTOT*CDIM];
__device__ float g_Y  [(size_t)MTOT*CDIM];
__device__ float g_YN [(size_t)MTOT*CDIM];
/* bf16 hi/lo splits */
__device__ __nv_bfloat16 g_XIH[(size_t)MTOT*CDIM];
__device__ __nv_bfloat16 g_XIL[(size_t)MTOT*CDIM];
__device__ __nv_bfloat16 g_YH [(size_t)MTOT*CDIM];
__device__ __nv_bfloat16 g_YL [(size_t)MTOT*CDIM];
__device__ __nv_bfloat16 g_XWH[(size_t)MTOT*CDIM];
__device__ __nv_bfloat16 g_XWL[(size_t)MTOT*CDIM];
__device__ __nv_bfloat16 g_VWH[(size_t)CDIM*CDIM];
__device__ __nv_bfloat16 g_VWL[(size_t)CDIM*CDIM];
__device__ __nv_bfloat16 g_OWH[(size_t)CDIM*CDIM];
__device__ __nv_bfloat16 g_OWL[(size_t)CDIM*CDIM];
/* transposed weight splits: [N, K] layout */
__device__ __nv_bfloat16 g_W1TH[(size_t)128*CDIM];
__device__ __nv_bfloat16 g_W1TL[(size_t)128*CDIM];
__device__ __nv_bfloat16 g_DW1TH[(size_t)128*CDIM];
__device__ __nv_bfloat16 g_DW1TL[(size_t)128*CDIM];

/* ================= bf16-split WMMA GEMM (NT) — R10-exact core ==============
   C[m,n] = sum_k A[m,k]*B[n,k],  A = AH+AL, B = BH+BL (bf16 hi/lo).
   Accumulate AH*BH + AH*BL + AL*BH in fp32 (lo*lo term dropped).
   Block 128x128, 8 warps (2x4), warp tile 64x32, K-chunk 32, register
   prefetch of chunk c+1 under chunk c's HMMA phase. epi: 0=none, 1=tanh. */
#define WLD 40   /* smem row pitch in bf16 */

__global__ __launch_bounds__(256)
void gemm_wmma3(const __nv_bfloat16* __restrict__ AH, const __nv_bfloat16* __restrict__ AL,
                const __nv_bfloat16* __restrict__ BH, const __nv_bfloat16* __restrict__ BL,
                float* __restrict__ C, int M, int N, int K, int epi)
{
    __shared__ __nv_bfloat16 AsH[128][WLD];
    __shared__ __nv_bfloat16 AsL[128][WLD];
    __shared__ __nv_bfloat16 BsH[128][WLD];
    __shared__ __nv_bfloat16 BsL[128][WLD];

    const int tid = threadIdx.x;
    const int wid = tid >> 5;
    const int wm = wid & 1;        /* 0..1  -> 64-row slab  */
    const int wn = wid >> 1;       /* 0..3  -> 32-col slab  */
    const int bm = blockIdx.y * 128;
    const int bn = blockIdx.x * 128;

    wmma::fragment<wmma::accumulator, 16, 16, 16, float> acc[4][2];
#pragma unroll
    for (int i = 0; i < 4; i++)
#pragma unroll
        for (int j = 0; j < 2; j++) wmma::fill_fragment(acc[i][j], 0.f);

    /* loader mapping: i = tid + u*256 -> row = i>>2, col8 = (i&3)*8 */
    int lrow[2], lc8[2];
#pragma unroll
    for (int u = 0; u < 2; u++) {
        int i = tid + (u << 8);
        lrow[u] = i >> 2;
        lc8[u]  = (i & 3) << 3;
    }

    uint4 pAH[2], pAL[2], pBH[2], pBL[2];
#pragma unroll
    for (int u = 0; u < 2; u++) {
        size_t sa = (size_t)(bm + lrow[u]) * K + lc8[u];
        size_t sb = (size_t)(bn + lrow[u]) * K + lc8[u];
        pAH[u] = *(const uint4*)(AH + sa);
        pAL[u] = *(const uint4*)(AL + sa);
        pBH[u] = *(const uint4*)(BH + sb);
        pBL[u] = *(const uint4*)(BL + sb);
    }

    const int nchunks = K >> 5;
    for (int c = 0; c < nchunks; c++) {
#pragma unroll
        for (int u = 0; u < 2; u++) {
            *(uint4*)&AsH[lrow[u]][lc8[u]] = pAH[u];
            *(uint4*)&AsL[lrow[u]][lc8[u]] = pAL[u];
            *(uint4*)&BsH[lrow[u]][lc8[u]] = pBH[u];
            *(uint4*)&BsL[lrow[u]][lc8[u]] = pBL[u];
        }
        __syncthreads();

        if (c + 1 < nchunks) {
            const int k0 = (c + 1) << 5;
#pragma unroll
            for (int u = 0; u < 2; u++) {
                size_t sa = (size_t)(bm + lrow[u]) * K + k0 + lc8[u];
                size_t sb = (size_t)(bn + lrow[u]) * K + k0 + lc8[u];
                pAH[u] = *(const uint4*)(AH + sa);
                pAL[u] = *(const uint4*)(AL + sa);
                pBH[u] = *(const uint4*)(BH + sb);
                pBL[u] = *(const uint4*)(BL + sb);
            }
        }

#pragma unroll
        for (int ks = 0; ks < 2; ks++) {
            wmma::fragment<wmma::matrix_b, 16, 16, 16, __nv_bfloat16, wmma::col_major> bh[2], bl[2];
#pragma unroll
            for (int j = 0; j < 2; j++) {
                wmma::load_matrix_sync(bh[j], &BsH[wn*32 + j*16][ks*16], WLD);
                wmma::load_matrix_sync(bl[j], &BsL[wn*32 + j*16][ks*16], WLD);
            }
#pragma unroll
            for (int i = 0; i < 4; i++) {
                wmma::fragment<wmma::matrix_a, 16, 16, 16, __nv_bfloat16, wmma::row_major> ah, al;
                wmma::load_matrix_sync(ah, &AsH[wm*64 + i*16][ks*16], WLD);
                wmma::load_matrix_sync(al, &AsL[wm*64 + i*16][ks*16], WLD);
#pragma unroll
                for (int j = 0; j < 2; j++) {
                    wmma::mma_sync(acc[i][j], ah, bh[j], acc[i][j]);
                    wmma::mma_sync(acc[i][j], ah, bl[j], acc[i][j]);
                    wmma::mma_sync(acc[i][j], al, bh[j], acc[i][j]);
                }
            }
        }
        __syncthreads();
    }

    if (epi == 1) {
#pragma unroll
        for (int i = 0; i < 4; i++)
#pragma unroll
            for (int j = 0; j < 2; j++)
                for (int e = 0; e < acc[i][j].num_elements; e++)
                    acc[i][j].x[e] = tanhf(acc[i][j].x[e]);
    }

#pragma unroll
    for (int i = 0; i < 4; i++)
#pragma unroll
        for (int j = 0; j < 2; j++)
            wmma::store_matrix_sync(&C[(size_t)(bm + wm*64 + i*16) * N + bn + wn*32 + j*16],
                                    acc[i][j], N, wmma::mem_row_major);
}

/* ---------------- fp32 -> bf16 hi/lo split (row-major preserving) ---------- */
__global__ void split_kernel(const float* __restrict__ in,
                             __nv_bfloat16* __restrict__ hi,
                             __nv_bfloat16* __restrict__ lo, int n4)
{
    int i = blockIdx.x * 256 + threadIdx.x;
    if (i >= n4) return;
    float4 x = ((const float4*)in)[i];
    __nv_bfloat16 h0 = __float2bfloat16(x.x), h1 = __float2bfloat16(x.y);
    __nv_bfloat16 h2 = __float2bfloat16(x.z), h3 = __float2bfloat16(x.w);
    __nv_bfloat162 hA; hA.x = h0; hA.y = h1;
    __nv_bfloat162 hB; hB.x = h2; hB.y = h3;
    __nv_bfloat162 lA; lA.x = __float2bfloat16(x.x - __bfloat162float(h0));
                       lA.y = __float2bfloat16(x.y - __bfloat162float(h1));
    __nv_bfloat162 lB; lB.x = __float2bfloat16(x.z - __bfloat162float(h2));
                       lB.y = __float2bfloat16(x.w - __bfloat162float(h3));
    ((__nv_bfloat162*)hi)[2*i]   = hA;
    ((__nv_bfloat162*)hi)[2*i+1] = hB;
    ((__nv_bfloat162*)lo)[2*i]   = lA;
    ((__nv_bfloat162*)lo)[2*i+1] = lB;
}

/* ---------------- [K,N] fp32 -> [N,K] bf16 hi/lo transpose-split ----------- */
__global__ void tsplit_kernel(const float* __restrict__ in,
                              __nv_bfloat16* __restrict__ hiT,
                              __nv_bfloat16* __restrict__ loT, int K, int N)
{
    int idx = blockIdx.x * 256 + threadIdx.x;
    if (idx >= K * N) return;
    int k = idx / N, n = idx % N;
    float v = in[idx];
    __nv_bfloat16 h = __float2bfloat16(v);
    hiT[(size_t)n * K + k] = h;
    loT[(size_t)n * K + k] = __float2bfloat16(v - __bfloat162float(h));
}

/* ---------------- generic NN GEMM: C[m,n] = f(sum_k A[m,lda..]*B[k,n]) ------
   epi: 0=none, 1=tanh, 2=exp(-exp(bias[n]+acc)),
        3=XW fusion: out = X + (Xprev - X) * (tmw[n] + acc), written as
          bf16 hi/lo to CH/CL (no fp32 write).                             */
__global__ __launch_bounds__(256, 2)
void gemm_nn(const float* __restrict__ A, int lda, int aoff,
             const float* __restrict__ B, int ldb,
             float* __restrict__ C, int ldc,
             int M, int N, int K, int epi, const float* __restrict__ bias,
             const float* __restrict__ Xf, const float* __restrict__ shf,
             const float* __restrict__ tw,
             __nv_bfloat16* __restrict__ CH, __nv_bfloat16* __restrict__ CL)
{
    __shared__ float As[64][36];
    __shared__ float Bs[32][128];
    const int tid = threadIdx.x;
    const int bm = blockIdx.y * 64;
    const int bn = blockIdx.x * 128;
    const int cx = tid & 31;
    const int rg = tid >> 5;

    float4 acc[8];
#pragma unroll
    for (int r = 0; r < 8; r++) acc[r] = make_float4(0.f,0.f,0.f,0.f);

    for (int k0 = 0; k0 < K; k0 += 32) {
#pragma unroll
        for (int u = 0; u < 2; u++) {
            int i = tid + 256*u;
            int r = i >> 3, kq = (i & 7) << 2;
            float4 v = *(const float4*)&A[(size_t)(bm + r) * lda + aoff + k0 + kq];
            *(float4*)&As[r][kq] = v;
        }
#pragma unroll
        for (int u = 0; u < 4; u++) {
            int i = tid + 256*u;
            int kr = i >> 5, nq = (i & 31) << 2;
            float4 v = make_float4(0.f,0.f,0.f,0.f);
            if (bn + nq < N)
                v = *(const float4*)&B[(size_t)(k0 + kr) * ldb + bn + nq];
            *(float4*)&Bs[kr][nq] = v;
        }
        __syncthreads();
#pragma unroll 8
        for (int k = 0; k < 32; k++) {
            float4 bv = *(const float4*)&Bs[k][cx << 2];
#pragma unroll
            for (int r = 0; r < 8; r++) {
                float a = As[rg*8 + r][k];
                acc[r].x = fmaf(a, bv.x, acc[r].x);
                acc[r].y = fmaf(a, bv.y, acc[r].y);
                acc[r].z = fmaf(a, bv.z, acc[r].z);
                acc[r].w = fmaf(a, bv.w, acc[r].w);
            }
        }
        __syncthreads();
    }
    const int n = bn + (cx << 2);
    if (n < N) {
#pragma unroll
        for (int r = 0; r < 8; r++) {
            float4 o = acc[r];
            const int m = bm + rg*8 + r;
            if (epi == 1) {
                o.x = tanhf(o.x); o.y = tanhf(o.y); o.z = tanhf(o.z); o.w = tanhf(o.w);
            } else if (epi == 2) {
                o.x = expf(-expf(bias[n+0] + o.x));
                o.y = expf(-expf(bias[n+1] + o.y));
                o.z = expf(-expf(bias[n+2] + o.z));
                o.w = expf(-expf(bias[n+3] + o.w));
            } else if (epi == 3) {
                const int t = m & (TLEN-1), b = m >> 11;
                float4 x  = *(const float4*)&Xf[(size_t)m * CDIM + n];
                float4 xp = (t == 0)
                    ? *(const float4*)&shf[(size_t)b * CDIM + n]
                    : *(const float4*)&Xf[(size_t)(m-1) * CDIM + n];
                float4 w  = *(const float4*)&tw[n];
                o.x = x.x + (xp.x - x.x) * (w.x + o.x);
                o.y = x.y + (xp.y - x.y) * (w.y + o.y);
                o.z = x.z + (xp.z - x.z) * (w.z + o.z);
                o.w = x.w + (xp.w - x.w) * (w.w + o.w);
                /* bf16 hi/lo write only */
                __nv_bfloat16 h0 = __float2bfloat16(o.x), h1 = __float2bfloat16(o.y);
                __nv_bfloat16 h2 = __float2bfloat16(o.z), h3 = __float2bfloat16(o.w);
                __nv_bfloat162 hA; hA.x = h0; hA.y = h1;
                __nv_bfloat162 hB; hB.x = h2; hB.y = h3;
                __nv_bfloat162 lA; lA.x = __float2bfloat16(o.x - __bfloat162float(h0));
                                   lA.y = __float2bfloat16(o.y - __bfloat162float(h1));
                __nv_bfloat162 lB; lB.x = __float2bfloat16(o.z - __bfloat162float(h2));
                                   lB.y = __float2bfloat16(o.w - __bfloat162float(h3));
                ((__nv_bfloat162*)&CH[(size_t)m * ldc + n])[0] = hA;
                ((__nv_bfloat162*)&CH[(size_t)m * ldc + n])[1] = hB;
                ((__nv_bfloat162*)&CL[(size_t)m * ldc + n])[0] = lA;
                ((__nv_bfloat162*)&CL[(size_t)m * ldc + n])[1] = lB;
                continue;
            }
            *(float4*)&C[(size_t)m * ldc + n] = o;
        }
    }
}

/* ---------------- elementwise: r, k, v, v2 --------------------------------- */
__global__ void ew_rkvv_kernel(const float* __restrict__ X, const float* __restrict__ shiftst,
    const float* __restrict__ M0, const float* __restrict__ M1,
    const float* __restrict__ M2, const float* __restrict__ M3,
    const float* __restrict__ DEC,
    const float* __restrict__ tmr, const float* __restrict__ tmk,
    const float* __restrict__ tmv, const float* __restrict__ tmv2,
    const float* __restrict__ trec, const float* __restrict__ tkey,
    float* __restrict__ R, float* __restrict__ K,
    float* __restrict__ V, float* __restrict__ V2)
{
    int i4 = blockIdx.x * 256 + threadIdx.x;
    int m = i4 >> 9, c4 = i4 & 511;
    int t = m & (TLEN-1), b = m >> 11;
    const float4* X4 = (const float4*)X;
    float4 x  = X4[i4];
    float4 xp = (t == 0) ? ((const float4*)shiftst)[(b << 9) + c4] : X4[i4 - 512];
    float4 m0 = ((const float4*)M0)[i4];
    float4 m1 = ((const float4*)M1)[i4];
    float4 m2 = ((const float4*)M2)[i4];
    float4 m3 = ((const float4*)M3)[i4];
    float4 d  = ((const float4*)DEC)[i4];
    float4 cr = ((const float4*)tmr)[c4];
    float4 ck = ((const float4*)tmk)[c4];
    float4 cv = ((const float4*)tmv)[c4];
    float4 c2 = ((const float4*)tmv2)[c4];
    float4 rc = ((const float4*)trec)[c4];
    float4 kc = ((const float4*)tkey)[c4];
    float4 o_r, o_k, o_v, o_w;
#define RKVV_APPLY(f) do { \
    float dxv = xp.f - x.f; \
    o_r.f = (x.f + dxv*(cr.f + m0.f)) * rc.f; \
    o_k.f = (x.f + dxv*(ck.f + m1.f)) * kc.f * (1.f - d.f); \
    o_v.f =  x.f + dxv*(cv.f + m2.f); \
    o_w.f =  x.f + dxv*(c2.f + m3.f); \
} while(0)
    RKVV_APPLY(x); RKVV_APPLY(y); RKVV_APPLY(z); RKVV_APPLY(w);
#undef RKVV_APPLY
    ((float4*)R )[i4] = o_r;
    ((float4*)K )[i4] = o_k;
    ((float4*)V )[i4] = o_v;
    ((float4*)V2)[i4] = o_w;
}

/* ---------------- WKV sequential scan, 8-step groups ----------------------- */
#define GSTEP 8
__global__ __launch_bounds__(256, 1)
void wkv_kernel(const float* __restrict__ Rp, const float* __restrict__ Kp,
                const float* __restrict__ Vp, const float* __restrict__ Dp,
                const float* __restrict__ S0, float* __restrict__ Y)
{
    const int bh = blockIdx.x;
    const int b = bh >> 5, h = bh & (NH-1);
    const int tid = threadIdx.x;
    const int j = tid >> 2, iq = tid & 3;

    float S[16];
    const float* s0p = S0 + (size_t)bh * HS * HS;
#pragma unroll
    for (int ii = 0; ii < 16; ii++) S[ii] = s0p[((iq << 4) + ii) * HS + j];

    __shared__ float sbuf[GSTEP][4][64];

    const int grp = tid >> 6, lane = tid & 63;
    const size_t base = ((size_t)b * TLEN) * CDIM + h * HS;
    const float* myp =
        ((grp == 0) ? Rp : (grp == 1) ? Kp : (grp == 2) ? Dp : Vp) + base + lane;

    float pre[GSTEP];
#pragma unroll
    for (int u = 0; u < GSTEP; u++) pre[u] = myp[(size_t)u * CDIM];

    const size_t ybase = base;
    for (int tc = 0; tc < TLEN; tc += GSTEP) {
#pragma unroll
        for (int u = 0; u < GSTEP; u++) sbuf[u][grp][lane] = pre[u];
        __syncthreads();
        if (tc + GSTEP < TLEN) {
#pragma unroll
            for (int u = 0; u < GSTEP; u++)
                pre[u] = myp[(size_t)(tc + GSTEP + u) * CDIM];
        }
#pragma unroll
        for (int u = 0; u < GSTEP; u++) {
            const float4* r4 = (const float4*)sbuf[u][0];
            const float4* k4 = (const float4*)sbuf[u][1];
            const float4* d4 = (const float4*)sbuf[u][2];
            const float vj = sbuf[u][3][j];
            float y = 0.f;
#pragma unroll
            for (int q = 0; q < 4; q++) {
                float4 rv = r4[iq*4 + q];
                y = fmaf(rv.x, S[q*4+0], y);
                y = fmaf(rv.y, S[q*4+1], y);
                y = fmaf(rv.z, S[q*4+2], y);
                y = fmaf(rv.w, S[q*4+3], y);
            }
#pragma unroll
            for (int q = 0; q < 4; q++) {
                float4 dv = d4[iq*4 + q];
                float4 kv = k4[iq*4 + q];
                S[q*4+0] = fmaf(dv.x, S[q*4+0], kv.x * vj);
                S[q*4+1] = fmaf(dv.y, S[q*4+1], kv.y * vj);
                S[q*4+2] = fmaf(dv.z, S[q*4+2], kv.z * vj);
                S[q*4+3] = fmaf(dv.w, S[q*4+3], kv.w * vj);
            }
            y += __shfl_xor_sync(0xffffffffu, y, 1);
            y += __shfl_xor_sync(0xffffffffu, y, 2);
            if (iq == 0) Y[ybase + (size_t)(tc + u) * CDIM + j] = y;
        }
        __syncthreads();
    }
}

/* ---------------- fused add + LayerNorm -> bf16 hi/lo ---------------------- */
__global__ void ln_kernel(const float* __restrict__ Y, const float* __restrict__ V2,
                          const float* __restrict__ gamma, const float* __restrict__ beta,
                          __nv_bfloat16* __restrict__ YH, __nv_bfloat16* __restrict__ YL)
{
    const int m = blockIdx.x;
    const int tid = threadIdx.x;
    const float4* y4 = (const float4*)(Y  + (size_t)m * CDIM);
    const float4* v4 = (const float4*)(V2 + (size_t)m * CDIM);
    float4 vals[2];
    float s = 0.f, s2 = 0.f;
#pragma unroll
    for (int u = 0; u < 2; u++) {
        float4 a = y4[tid + u*256], b = v4[tid + u*256];
        float4 v = make_float4(a.x+b.x, a.y+b.y, a.z+b.z, a.w+b.w);
        vals[u] = v;
        s  += v.x + v.y + v.z + v.w;
        s2 += v.x*v.x + v.y*v.y + v.z*v.z + v.w*v.w;
    }
#pragma unroll
    for (int o = 16; o; o >>= 1) {
        s  += __shfl_xor_sync(0xffffffffu, s,  o);
        s2 += __shfl_xor_sync(0xffffffffu, s2, o);
    }
    __shared__ float sh[2][8];
    const int w = tid >> 5, l = tid & 31;
    if (l == 0) { sh[0][w] = s; sh[1][w] = s2; }
    __syncthreads();
    s = 0.f; s2 = 0.f;
#pragma unroll
    for (int i = 0; i < 8; i++) { s += sh[0][i]; s2 += sh[1][i]; }
    const float mu   = s  * (1.f / CDIM);
    const float var  = s2 * (1.f / CDIM) - mu * mu;
    const float rstd = rsqrtf(var + 1e-5f);
    const float4* g4 = (const float4*)gamma;
    const float4* b4 = (const float4*)beta;
    __nv_bfloat162* yh2 = (__nv_bfloat162*)(YH + (size_t)m * CDIM);
    __nv_bfloat162* yl2 = (__nv_bfloat162*)(YL + (size_t)m * CDIM);
#pragma unroll
    for (int u = 0; u < 2; u++) {
        int c4 = tid + u*256;
        float4 g = g4[c4], bb = b4[c4], v = vals[u];
        float o0 = (v.x - mu) * rstd * g.x + bb.x;
        float o1 = (v.y - mu) * rstd * g.y + bb.y;
        float o2 = (v.z - mu) * rstd * g.z + bb.z;
        float o3 = (v.w - mu) * rstd * g.w + bb.w;
        __nv_bfloat16 h0 = __float2bfloat16(o0), h1 = __float2bfloat16(o1);
        __nv_bfloat16 h2 = __float2bfloat16(o2), h3 = __float2bfloat16(o3);
        __nv_bfloat162 hA; hA.x = h0; hA.y = h1;
        __nv_bfloat162 hB; hB.x = h2; hB.y = h3;
        __nv_bfloat162 lA; lA.x = __float2bfloat16(o0 - __bfloat162float(h0));
                           lA.y = __float2bfloat16(o1 - __bfloat162float(h1));
        __nv_bfloat162 lB; lB.x = __float2bfloat16(o2 - __bfloat162float(h2));
                           lB.y = __float2bfloat16(o3 - __bfloat162float(h3));
        yh2[2*c4]   = hA;  yh2[2*c4+1] = hB;
        yl2[2*c4]   = lA;  yl2[2*c4+1] = lB;
    }
}

/* ---------------- launch --------------------------------------------------- */
extern "C" void kernel_launch(void* const* d_in, const int* in_sizes, int n_in,
                              void* d_out, int out_size)
{
    const float* x_in     = (const float*)d_in[0];
    const float* shiftst  = (const float*)d_in[1];
    const float* wkvstate = (const float*)d_in[2];
    const float* tmr      = (const float*)d_in[3];
    const float* tmk      = (const float*)d_in[4];
    const float* tmv      = (const float*)d_in[5];
    const float* tmv2     = (const float*)d_in[6];
    const float* maa_w1   = (const float*)d_in[7];
    const float* maa_w2   = (const float*)d_in[8];
    const float* tmw      = (const float*)d_in[9];
    const float* ww1      = (const float*)d_in[10];
    const float* ww2      = (const float*)d_in[11];
    const float* tdecay   = (const float*)d_in[12];
    const float* dw1      = (const float*)d_in[13];
    const float* dw2      = (const float*)d_in[14];
    /* d_in[15] = time_faaaa: unused (u == 0 in this model) */
    const float* trec     = (const float*)d_in[16];
    const float* tkey     = (const float*)d_in[17];
    const float* value_w  = (const float*)d_in[18];
    const float* output_w = (const float*)d_in[19];
    const float* gamma    = (const float*)d_in[20];
    const float* beta     = (const float*)d_in[21];
    float* out = (float*)d_out;

    float *pX, *pXX1, *pMIX, *pXW1, *pT1, *pDEC, *pR, *pK, *pV, *pV2, *pY;
    __nv_bfloat16 *pXIH, *pXIL, *pYH, *pYL, *pXWH, *pXWL, *pVWH, *pVWL, *pOWH, *pOWL;
    __nv_bfloat16 *pW1TH, *pW1TL, *pDW1TH, *pDW1TL;
    cudaGetSymbolAddress((void**)&pX,   g_X);
    cudaGetSymbolAddress((void**)&pXX1, g_XX1);
    cudaGetSymbolAddress((void**)&pMIX, g_MIX);
    cudaGetSymbolAddress((void**)&pXW1, g_XW1);
    cudaGetSymbolAddress((void**)&pT1,  g_T1);
    cudaGetSymbolAddress((void**)&pDEC, g_DEC);
    cudaGetSymbolAddress((void**)&pR,   g_R);
    cudaGetSymbolAddress((void**)&pK,   g_K);
    cudaGetSymbolAddress((void**)&pV,   g_V);
    cudaGetSymbolAddress((void**)&pV2,  g_V2);
    cudaGetSymbolAddress((void**)&pY,   g_Y);
    cudaGetSymbolAddress((void**)&pXIH, g_XIH);
    cudaGetSymbolAddress((void**)&pXIL, g_XIL);
    cudaGetSymbolAddress((void**)&pYH,  g_YH);
    cudaGetSymbolAddress((void**)&pYL,  g_YL);
    cudaGetSymbolAddress((void**)&pXWH, g_XWH);
    cudaGetSymbolAddress((void**)&pXWL, g_XWL);
    cudaGetSymbolAddress((void**)&pVWH, g_VWH);
    cudaGetSymbolAddress((void**)&pVWL, g_VWL);
    cudaGetSymbolAddress((void**)&pOWH, g_OWH);
    cudaGetSymbolAddress((void**)&pOWL, g_OWL);
    cudaGetSymbolAddress((void**)&pW1TH,  g_W1TH);
    cudaGetSymbolAddress((void**)&pW1TL,  g_W1TL);
    cudaGetSymbolAddress((void**)&pDW1TH, g_DW1TH);
    cudaGetSymbolAddress((void**)&pDW1TL, g_DW1TL);

    const size_t SZ = (size_t)MTOT * CDIM;
    const int EW_BLOCKS = (int)(SZ / 4 / 256);
    const int SPLIT_BLK_X  = (int)(SZ / 4 / 256);
    const int SPLIT_BLK_W  = (int)((size_t)CDIM * CDIM / 4 / 256);
    const int TS_BLKS = (CDIM * 128 + 255) / 256;
    const float* NUL = (const float*)0;
    __nv_bfloat16* NB = (__nv_bfloat16*)0;

    /* 0-2: bf16 hi/lo splits */
    split_kernel<<<SPLIT_BLK_X, 256>>>(x_in, pXIH, pXIL, (int)(SZ / 4));
    split_kernel<<<SPLIT_BLK_W, 256>>>(value_w,  pVWH, pVWL, (int)((size_t)CDIM*CDIM/4));
    split_kernel<<<SPLIT_BLK_W, 256>>>(output_w, pOWH, pOWL, (int)((size_t)CDIM*CDIM/4));
    /* 3-4: weight transpose-splits [K,N] -> [N,K] */
    tsplit_kernel<<<TS_BLKS, 256>>>(maa_w1, pW1TH, pW1TL, CDIM, 128);
    tsplit_kernel<<<TS_BLKS, 256>>>(dw1,    pDW1TH, pDW1TL, CDIM, 128);

    /* 5: XX1 = tanh(x_in @ maa_w1)  (wmma bf16x3, N=128) <- ncu catches this */
    gemm_wmma3<<<dim3(1, MTOT/128), 256>>>(pXIH, pXIL, pW1TH, pW1TL, pXX1,
                                           MTOT, 128, CDIM, 1);

    /* 6: X = x_in @ value_w^T */
    gemm_wmma3<<<dim3(CDIM/128, MTOT/128), 256>>>(pXIH, pXIL, pVWH, pVWL, pX,
                                                  MTOT, CDIM, CDIM, 0);

    /* 7-10: MIX[f] = XX1[:, f*32:(f+1)*32] @ maa_w2[f] */
    for (int f = 0; f < 4; f++)
        gemm_nn<<<dim3(CDIM/128, MTOT/64), 256>>>(pXX1, 128, f*32,
                                                  maa_w2 + (size_t)f*32*CDIM, CDIM,
                                                  pMIX + (size_t)f*SZ, CDIM,
                                                  MTOT, CDIM, 32, 0, NUL, NUL, NUL, NUL, NB, NB);
    /* 11: XW1 = tanh(X @ w_w1) */
    gemm_nn<<<dim3(1, MTOT/64), 256>>>(pX, CDIM, 0, ww1, 32, pXW1, 32,
                                       MTOT, 32, CDIM, 1, NUL, NUL, NUL, NUL, NB, NB);
    /* 12: XW = X + dxprev*(time_maa_w + XW1 @ w_w2) -> bf16 hi/lo (epi=3) */
    gemm_nn<<<dim3(CDIM/128, MTOT/64), 256>>>(pXW1, 32, 0, ww2, CDIM, NUL ? 0 : (float*)0, CDIM,
                                              MTOT, CDIM, 32, 3, NUL,
                                              pX, shiftst, tmw, pXWH, pXWL);
    /* 13: T1 = tanh(XW @ decay_w1)  (wmma bf16x3, N=128) */
    gemm_wmma3<<<dim3(1, MTOT/128), 256>>>(pXWH, pXWL, pDW1TH, pDW1TL, pT1,
                                           MTOT, 128, CDIM, 1);
    /* 14: DEC = exp(-exp(time_decay + T1 @ decay_w2)) */
    gemm_nn<<<dim3(CDIM/128, MTOT/64), 256>>>(pT1, 128, 0, dw2, CDIM, pDEC, CDIM,
                                              MTOT, CDIM, 128, 2, tdecay, NUL, NUL, NUL, NB, NB);
    /* 15: r, k, v, v2 */
    ew_rkvv_kernel<<<EW_BLOCKS, 256>>>(pX, shiftst,
                                       pMIX, pMIX + SZ, pMIX + 2*SZ, pMIX + 3*SZ,
                                       pDEC, tmr, tmk, tmv, tmv2, trec, tkey,
                                       pR, pK, pV, pV2);
    /* 16: WKV scan (8-step groups) */
    wkv_kernel<<<BATCH*NH, 256>>>(pR, pK, pV, pDEC, wkvstate, pY);
    /* 17: yn = LN(y + v2) -> bf16 hi/lo */
    ln_kernel<<<MTOT, 256>>>(pY, pV2, gamma, beta, pYH, pYL);
    /* 18: out = yn @ output_w^T */
    gemm_wmma3<<<dim3(CDIM/128, MTOT/128), 256>>>(pYH, pYL, pOWH, pOWL, out,
                                                  MTOT, CDIM, CDIM, 0);
}

// round 15
// speedup vs baseline: 1.0914x; 1.0406x over previous
#include <cuda_runtime.h>
#include <cuda_bf16.h>
#include <mma.h>
#include <math.h>
#include <stdint.h>

using namespace nvcuda;

#define BATCH 4
#define TLEN  2048
#define CDIM  2048
#define HS    64
#define NH    32
#define MTOT  (BATCH*TLEN)   /* 8192 */

/* ---------------- scratch (static device allocations; no cudaMalloc) ------- */
__device__ float g_X  [(size_t)MTOT*CDIM];
__device__ float g_XX1[(size_t)MTOT*128];
__device__ float g_XW1[(size_t)MTOT*32];
__device__ float g_T1 [(size_t)MTOT*128];
__device__ float g_DEC[(size_t)MTOT*CDIM];
__device__ float g_R  [(size_t)MTOT*CDIM];
__device__ float g_K  [(size_t)MTOT*CDIM];
__device__ float g_V  [(size_t)MTOT*CDIM];
__device__ float g_V2 [(size_t)MTOT*CDIM];
__device__ float g_Y  [(size_t)MTOT*CDIM];
/* bf16 hi/lo splits */
__device__ __nv_bfloat16 g_XIH[(size_t)MTOT*CDIM];
__device__ __nv_bfloat16 g_XIL[(size_t)MTOT*CDIM];
__device__ __nv_bfloat16 g_YH [(size_t)MTOT*CDIM];
__device__ __nv_bfloat16 g_YL [(size_t)MTOT*CDIM];
__device__ __nv_bfloat16 g_XWH[(size_t)MTOT*CDIM];
__device__ __nv_bfloat16 g_XWL[(size_t)MTOT*CDIM];
__device__ __nv_bfloat16 g_VWH[(size_t)CDIM*CDIM];
__device__ __nv_bfloat16 g_VWL[(size_t)CDIM*CDIM];
__device__ __nv_bfloat16 g_OWH[(size_t)CDIM*CDIM];
__device__ __nv_bfloat16 g_OWL[(size_t)CDIM*CDIM];
/* transposed weight splits: [N, K] layout */
__device__ __nv_bfloat16 g_W1TH[(size_t)128*CDIM];
__device__ __nv_bfloat16 g_W1TL[(size_t)128*CDIM];
__device__ __nv_bfloat16 g_DW1TH[(size_t)128*CDIM];
__device__ __nv_bfloat16 g_DW1TL[(size_t)128*CDIM];

#define WLD 40   /* smem row pitch in bf16 */

/* ================= bf16-split WMMA GEMM (NT) — R10-exact core ==============
   Block 128x128, 8 warps (2x4), warp tile 64x32, K-chunk 32, register
   prefetch. AH*BH + AH*BL + AL*BH accumulated fp32.                      */
__global__ __launch_bounds__(256)
void gemm_wmma3(const __nv_bfloat16* __restrict__ AH, const __nv_bfloat16* __restrict__ AL,
                const __nv_bfloat16* __restrict__ BH, const __nv_bfloat16* __restrict__ BL,
                float* __restrict__ C, int M, int N, int K)
{
    __shared__ __nv_bfloat16 AsH[128][WLD];
    __shared__ __nv_bfloat16 AsL[128][WLD];
    __shared__ __nv_bfloat16 BsH[128][WLD];
    __shared__ __nv_bfloat16 BsL[128][WLD];

    const int tid = threadIdx.x;
    const int wid = tid >> 5;
    const int wm = wid & 1;
    const int wn = wid >> 1;
    const int bm = blockIdx.y * 128;
    const int bn = blockIdx.x * 128;

    wmma::fragment<wmma::accumulator, 16, 16, 16, float> acc[4][2];
#pragma unroll
    for (int i = 0; i < 4; i++)
#pragma unroll
        for (int j = 0; j < 2; j++) wmma::fill_fragment(acc[i][j], 0.f);

    int lrow[2], lc8[2];
#pragma unroll
    for (int u = 0; u < 2; u++) {
        int i = tid + (u << 8);
        lrow[u] = i >> 2;
        lc8[u]  = (i & 3) << 3;
    }

    uint4 pAH[2], pAL[2], pBH[2], pBL[2];
#pragma unroll
    for (int u = 0; u < 2; u++) {
        size_t sa = (size_t)(bm + lrow[u]) * K + lc8[u];
        size_t sb = (size_t)(bn + lrow[u]) * K + lc8[u];
        pAH[u] = *(const uint4*)(AH + sa);
        pAL[u] = *(const uint4*)(AL + sa);
        pBH[u] = *(const uint4*)(BH + sb);
        pBL[u] = *(const uint4*)(BL + sb);
    }

    const int nchunks = K >> 5;
    for (int c = 0; c < nchunks; c++) {
#pragma unroll
        for (int u = 0; u < 2; u++) {
            *(uint4*)&AsH[lrow[u]][lc8[u]] = pAH[u];
            *(uint4*)&AsL[lrow[u]][lc8[u]] = pAL[u];
            *(uint4*)&BsH[lrow[u]][lc8[u]] = pBH[u];
            *(uint4*)&BsL[lrow[u]][lc8[u]] = pBL[u];
        }
        __syncthreads();

        if (c + 1 < nchunks) {
            const int k0 = (c + 1) << 5;
#pragma unroll
            for (int u = 0; u < 2; u++) {
                size_t sa = (size_t)(bm + lrow[u]) * K + k0 + lc8[u];
                size_t sb = (size_t)(bn + lrow[u]) * K + k0 + lc8[u];
                pAH[u] = *(const uint4*)(AH + sa);
                pAL[u] = *(const uint4*)(AL + sa);
                pBH[u] = *(const uint4*)(BH + sb);
                pBL[u] = *(const uint4*)(BL + sb);
            }
        }

#pragma unroll
        for (int ks = 0; ks < 2; ks++) {
            wmma::fragment<wmma::matrix_b, 16, 16, 16, __nv_bfloat16, wmma::col_major> bh[2], bl[2];
#pragma unroll
            for (int j = 0; j < 2; j++) {
                wmma::load_matrix_sync(bh[j], &BsH[wn*32 + j*16][ks*16], WLD);
                wmma::load_matrix_sync(bl[j], &BsL[wn*32 + j*16][ks*16], WLD);
            }
#pragma unroll
            for (int i = 0; i < 4; i++) {
                wmma::fragment<wmma::matrix_a, 16, 16, 16, __nv_bfloat16, wmma::row_major> ah, al;
                wmma::load_matrix_sync(ah, &AsH[wm*64 + i*16][ks*16], WLD);
                wmma::load_matrix_sync(al, &AsL[wm*64 + i*16][ks*16], WLD);
#pragma unroll
                for (int j = 0; j < 2; j++) {
                    wmma::mma_sync(acc[i][j], ah, bh[j], acc[i][j]);
                    wmma::mma_sync(acc[i][j], ah, bl[j], acc[i][j]);
                    wmma::mma_sync(acc[i][j], al, bh[j], acc[i][j]);
                }
            }
        }
        __syncthreads();
    }

#pragma unroll
    for (int i = 0; i < 4; i++)
#pragma unroll
        for (int j = 0; j < 2; j++)
            wmma::store_matrix_sync(&C[(size_t)(bm + wm*64 + i*16) * N + bn + wn*32 + j*16],
                                    acc[i][j], N, wmma::mem_row_major);
}

/* ================= skinny variant: BM=64, BN=128 (N==128), tanh epilogue ===
   Doubles grid occupancy for the two M x 128 x 2048 GEMMs (128 blocks).  */
__global__ __launch_bounds__(256)
void gemm_wmma3_skinny(const __nv_bfloat16* __restrict__ AH, const __nv_bfloat16* __restrict__ AL,
                       const __nv_bfloat16* __restrict__ BH, const __nv_bfloat16* __restrict__ BL,
                       float* __restrict__ C, int M, int K)
{
    __shared__ __nv_bfloat16 AsH[64][WLD];
    __shared__ __nv_bfloat16 AsL[64][WLD];
    __shared__ __nv_bfloat16 BsH[128][WLD];
    __shared__ __nv_bfloat16 BsL[128][WLD];

    const int tid = threadIdx.x;
    const int wid = tid >> 5;
    const int wm = wid & 1;        /* 0..1 -> 32-row slab */
    const int wn = wid >> 1;       /* 0..3 -> 32-col slab */
    const int bm = blockIdx.y * 64;

    wmma::fragment<wmma::accumulator, 16, 16, 16, float> acc[2][2];
#pragma unroll
    for (int i = 0; i < 2; i++)
#pragma unroll
        for (int j = 0; j < 2; j++) wmma::fill_fragment(acc[i][j], 0.f);

    const int larA = tid >> 2, lcA = (tid & 3) << 3;   /* 64 rows x 4 uint4 */
    int lrB[2], lcB[2];
#pragma unroll
    for (int u = 0; u < 2; u++) {
        int i = tid + (u << 8);
        lrB[u] = i >> 2;
        lcB[u] = (i & 3) << 3;
    }

    uint4 pAH, pAL, pBH[2], pBL[2];
    {
        size_t sa = (size_t)(bm + larA) * K + lcA;
        pAH = *(const uint4*)(AH + sa);
        pAL = *(const uint4*)(AL + sa);
#pragma unroll
        for (int u = 0; u < 2; u++) {
            size_t sb = (size_t)lrB[u] * K + lcB[u];
            pBH[u] = *(const uint4*)(BH + sb);
            pBL[u] = *(const uint4*)(BL + sb);
        }
    }

    const int nchunks = K >> 5;
    for (int c = 0; c < nchunks; c++) {
        *(uint4*)&AsH[larA][lcA] = pAH;
        *(uint4*)&AsL[larA][lcA] = pAL;
#pragma unroll
        for (int u = 0; u < 2; u++) {
            *(uint4*)&BsH[lrB[u]][lcB[u]] = pBH[u];
            *(uint4*)&BsL[lrB[u]][lcB[u]] = pBL[u];
        }
        __syncthreads();

        if (c + 1 < nchunks) {
            const int k0 = (c + 1) << 5;
            size_t sa = (size_t)(bm + larA) * K + k0 + lcA;
            pAH = *(const uint4*)(AH + sa);
            pAL = *(const uint4*)(AL + sa);
#pragma unroll
            for (int u = 0; u < 2; u++) {
                size_t sb = (size_t)lrB[u] * K + k0 + lcB[u];
                pBH[u] = *(const uint4*)(BH + sb);
                pBL[u] = *(const uint4*)(BL + sb);
            }
        }

#pragma unroll
        for (int ks = 0; ks < 2; ks++) {
            wmma::fragment<wmma::matrix_b, 16, 16, 16, __nv_bfloat16, wmma::col_major> bh[2], bl[2];
#pragma unroll
            for (int j = 0; j < 2; j++) {
                wmma::load_matrix_sync(bh[j], &BsH[wn*32 + j*16][ks*16], WLD);
                wmma::load_matrix_sync(bl[j], &BsL[wn*32 + j*16][ks*16], WLD);
            }
#pragma unroll
            for (int i = 0; i < 2; i++) {
                wmma::fragment<wmma::matrix_a, 16, 16, 16, __nv_bfloat16, wmma::row_major> ah, al;
                wmma::load_matrix_sync(ah, &AsH[wm*32 + i*16][ks*16], WLD);
                wmma::load_matrix_sync(al, &AsL[wm*32 + i*16][ks*16], WLD);
#pragma unroll
                for (int j = 0; j < 2; j++) {
                    wmma::mma_sync(acc[i][j], ah, bh[j], acc[i][j]);
                    wmma::mma_sync(acc[i][j], ah, bl[j], acc[i][j]);
                    wmma::mma_sync(acc[i][j], al, bh[j], acc[i][j]);
                }
            }
        }
        __syncthreads();
    }

#pragma unroll
    for (int i = 0; i < 2; i++)
#pragma unroll
        for (int j = 0; j < 2; j++) {
            for (int e = 0; e < acc[i][j].num_elements; e++)
                acc[i][j].x[e] = tanhf(acc[i][j].x[e]);
            wmma::store_matrix_sync(&C[(size_t)(bm + wm*32 + i*16) * 128 + wn*32 + j*16],
                                    acc[i][j], 128, wmma::mem_row_major);
        }
}

/* ---------------- fp32 -> bf16 hi/lo split --------------------------------- */
__global__ void split_kernel(const float* __restrict__ in,
                             __nv_bfloat16* __restrict__ hi,
                             __nv_bfloat16* __restrict__ lo, int n4)
{
    int i = blockIdx.x * 256 + threadIdx.x;
    if (i >= n4) return;
    float4 x = ((const float4*)in)[i];
    __nv_bfloat16 h0 = __float2bfloat16(x.x), h1 = __float2bfloat16(x.y);
    __nv_bfloat16 h2 = __float2bfloat16(x.z), h3 = __float2bfloat16(x.w);
    __nv_bfloat162 hA; hA.x = h0; hA.y = h1;
    __nv_bfloat162 hB; hB.x = h2; hB.y = h3;
    __nv_bfloat162 lA; lA.x = __float2bfloat16(x.x - __bfloat162float(h0));
                       lA.y = __float2bfloat16(x.y - __bfloat162float(h1));
    __nv_bfloat162 lB; lB.x = __float2bfloat16(x.z - __bfloat162float(h2));
                       lB.y = __float2bfloat16(x.w - __bfloat162float(h3));
    ((__nv_bfloat162*)hi)[2*i]   = hA;
    ((__nv_bfloat162*)hi)[2*i+1] = hB;
    ((__nv_bfloat162*)lo)[2*i]   = lA;
    ((__nv_bfloat162*)lo)[2*i+1] = lB;
}

/* ---------------- [K,N] fp32 -> [N,K] bf16 hi/lo transpose-split ----------- */
__global__ void tsplit_kernel(const float* __restrict__ in,
                              __nv_bfloat16* __restrict__ hiT,
                              __nv_bfloat16* __restrict__ loT, int K, int N)
{
    int idx = blockIdx.x * 256 + threadIdx.x;
    if (idx >= K * N) return;
    int k = idx / N, n = idx % N;
    float v = in[idx];
    __nv_bfloat16 h = __float2bfloat16(v);
    hiT[(size_t)n * K + k] = h;
    loT[(size_t)n * K + k] = __float2bfloat16(v - __bfloat162float(h));
}

/* ---------------- generic NN GEMM: C[m,n] = f(sum_k A[m,lda..]*B[k,n]) ------
   epi: 0=none, 1=tanh, 2=exp(-exp(bias[n]+acc)),
        3=XW fusion -> bf16 hi/lo CH/CL,
        4=x + dx*(bias[n]+acc)                       (V, V2)
        5=(x + dx*(bias[n]+acc)) * tw[n]             (R)
        6=(x + dx*(bias[n]+acc)) * tw[n] * (1-dec)   (K)                   */
__global__ __launch_bounds__(256, 2)
void gemm_nn(const float* __restrict__ A, int lda, int aoff,
             const float* __restrict__ B, int ldb,
             float* __restrict__ C, int ldc,
             int M, int N, int K, int epi, const float* __restrict__ bias,
             const float* __restrict__ Xf, const float* __restrict__ shf,
             const float* __restrict__ tw,
             __nv_bfloat16* __restrict__ CH, __nv_bfloat16* __restrict__ CL,
             const float* __restrict__ decp)
{
    __shared__ float As[64][36];
    __shared__ float Bs[32][128];
    const int tid = threadIdx.x;
    const int bm = blockIdx.y * 64;
    const int bn = blockIdx.x * 128;
    const int cx = tid & 31;
    const int rg = tid >> 5;

    float4 acc[8];
#pragma unroll
    for (int r = 0; r < 8; r++) acc[r] = make_float4(0.f,0.f,0.f,0.f);

    for (int k0 = 0; k0 < K; k0 += 32) {
#pragma unroll
        for (int u = 0; u < 2; u++) {
            int i = tid + 256*u;
            int r = i >> 3, kq = (i & 7) << 2;
            float4 v = *(const float4*)&A[(size_t)(bm + r) * lda + aoff + k0 + kq];
            *(float4*)&As[r][kq] = v;
        }
#pragma unroll
        for (int u = 0; u < 4; u++) {
            int i = tid + 256*u;
            int kr = i >> 5, nq = (i & 31) << 2;
            float4 v = make_float4(0.f,0.f,0.f,0.f);
            if (bn + nq < N)
                v = *(const float4*)&B[(size_t)(k0 + kr) * ldb + bn + nq];
            *(float4*)&Bs[kr][nq] = v;
        }
        __syncthreads();
#pragma unroll 8
        for (int k = 0; k < 32; k++) {
            float4 bv = *(const float4*)&Bs[k][cx << 2];
#pragma unroll
            for (int r = 0; r < 8; r++) {
                float a = As[rg*8 + r][k];
                acc[r].x = fmaf(a, bv.x, acc[r].x);
                acc[r].y = fmaf(a, bv.y, acc[r].y);
                acc[r].z = fmaf(a, bv.z, acc[r].z);
                acc[r].w = fmaf(a, bv.w, acc[r].w);
            }
        }
        __syncthreads();
    }
    const int n = bn + (cx << 2);
    if (n < N) {
#pragma unroll
        for (int r = 0; r < 8; r++) {
            float4 o = acc[r];
            const int m = bm + rg*8 + r;
            if (epi == 1) {
                o.x = tanhf(o.x); o.y = tanhf(o.y); o.z = tanhf(o.z); o.w = tanhf(o.w);
            } else if (epi == 2) {
                o.x = expf(-expf(bias[n+0] + o.x));
                o.y = expf(-expf(bias[n+1] + o.y));
                o.z = expf(-expf(bias[n+2] + o.z));
                o.w = expf(-expf(bias[n+3] + o.w));
            } else if (epi == 3) {
                const int t = m & (TLEN-1), b = m >> 11;
                float4 x  = *(const float4*)&Xf[(size_t)m * CDIM + n];
                float4 xp = (t == 0)
                    ? *(const float4*)&shf[(size_t)b * CDIM + n]
                    : *(const float4*)&Xf[(size_t)(m-1) * CDIM + n];
                float4 w  = *(const float4*)&tw[n];
                o.x = x.x + (xp.x - x.x) * (w.x + o.x);
                o.y = x.y + (xp.y - x.y) * (w.y + o.y);
                o.z = x.z + (xp.z - x.z) * (w.z + o.z);
                o.w = x.w + (xp.w - x.w) * (w.w + o.w);
                __nv_bfloat16 h0 = __float2bfloat16(o.x), h1 = __float2bfloat16(o.y);
                __nv_bfloat16 h2 = __float2bfloat16(o.z), h3 = __float2bfloat16(o.w);
                __nv_bfloat162 hA; hA.x = h0; hA.y = h1;
                __nv_bfloat162 hB; hB.x = h2; hB.y = h3;
                __nv_bfloat162 lA; lA.x = __float2bfloat16(o.x - __bfloat162float(h0));
                                   lA.y = __float2bfloat16(o.y - __bfloat162float(h1));
                __nv_bfloat162 lB; lB.x = __float2bfloat16(o.z - __bfloat162float(h2));
                                   lB.y = __float2bfloat16(o.w - __bfloat162float(h3));
                ((__nv_bfloat162*)&CH[(size_t)m * ldc + n])[0] = hA;
                ((__nv_bfloat162*)&CH[(size_t)m * ldc + n])[1] = hB;
                ((__nv_bfloat162*)&CL[(size_t)m * ldc + n])[0] = lA;
                ((__nv_bfloat162*)&CL[(size_t)m * ldc + n])[1] = lB;
                continue;
            } else if (epi >= 4) {
                const int t = m & (TLEN-1), b = m >> 11;
                float4 x  = *(const float4*)&Xf[(size_t)m * CDIM + n];
                float4 xp = (t == 0)
                    ? *(const float4*)&shf[(size_t)b * CDIM + n]
                    : *(const float4*)&Xf[(size_t)(m-1) * CDIM + n];
                float4 cb = *(const float4*)&bias[n];
                o.x = x.x + (xp.x - x.x) * (cb.x + o.x);
                o.y = x.y + (xp.y - x.y) * (cb.y + o.y);
                o.z = x.z + (xp.z - x.z) * (cb.z + o.z);
                o.w = x.w + (xp.w - x.w) * (cb.w + o.w);
                if (epi >= 5) {
                    float4 sc = *(const float4*)&tw[n];
                    o.x *= sc.x; o.y *= sc.y; o.z *= sc.z; o.w *= sc.w;
                }
                if (epi == 6) {
                    float4 d = *(const float4*)&decp[(size_t)m * CDIM + n];
                    o.x *= (1.f - d.x); o.y *= (1.f - d.y);
                    o.z *= (1.f - d.z); o.w *= (1.f - d.w);
                }
            }
            *(float4*)&C[(size_t)m * ldc + n] = o;
        }
    }
}

/* ---------------- WKV sequential scan, 8-step groups ----------------------- */
#define GSTEP 8
__global__ __launch_bounds__(256, 1)
void wkv_kernel(const float* __restrict__ Rp, const float* __restrict__ Kp,
                const float* __restrict__ Vp, const float* __restrict__ Dp,
                const float* __restrict__ S0, float* __restrict__ Y)
{
    const int bh = blockIdx.x;
    const int b = bh >> 5, h = bh & (NH-1);
    const int tid = threadIdx.x;
    const int j = tid >> 2, iq = tid & 3;

    float S[16];
    const float* s0p = S0 + (size_t)bh * HS * HS;
#pragma unroll
    for (int ii = 0; ii < 16; ii++) S[ii] = s0p[((iq << 4) + ii) * HS + j];

    __shared__ float sbuf[GSTEP][4][64];

    const int grp = tid >> 6, lane = tid & 63;
    const size_t base = ((size_t)b * TLEN) * CDIM + h * HS;
    const float* myp =
        ((grp == 0) ? Rp : (grp == 1) ? Kp : (grp == 2) ? Dp : Vp) + base + lane;

    float pre[GSTEP];
#pragma unroll
    for (int u = 0; u < GSTEP; u++) pre[u] = myp[(size_t)u * CDIM];

    const size_t ybase = base;
    for (int tc = 0; tc < TLEN; tc += GSTEP) {
#pragma unroll
        for (int u = 0; u < GSTEP; u++) sbuf[u][grp][lane] = pre[u];
        __syncthreads();
        if (tc + GSTEP < TLEN) {
#pragma unroll
            for (int u = 0; u < GSTEP; u++)
                pre[u] = myp[(size_t)(tc + GSTEP + u) * CDIM];
        }
#pragma unroll
        for (int u = 0; u < GSTEP; u++) {
            const float4* r4 = (const float4*)sbuf[u][0];
            const float4* k4 = (const float4*)sbuf[u][1];
            const float4* d4 = (const float4*)sbuf[u][2];
            const float vj = sbuf[u][3][j];
            float y = 0.f;
#pragma unroll
            for (int q = 0; q < 4; q++) {
                float4 rv = r4[iq*4 + q];
                y = fmaf(rv.x, S[q*4+0], y);
                y = fmaf(rv.y, S[q*4+1], y);
                y = fmaf(rv.z, S[q*4+2], y);
                y = fmaf(rv.w, S[q*4+3], y);
            }
#pragma unroll
            for (int q = 0; q < 4; q++) {
                float4 dv = d4[iq*4 + q];
                float4 kv = k4[iq*4 + q];
                S[q*4+0] = fmaf(dv.x, S[q*4+0], kv.x * vj);
                S[q*4+1] = fmaf(dv.y, S[q*4+1], kv.y * vj);
                S[q*4+2] = fmaf(dv.z, S[q*4+2], kv.z * vj);
                S[q*4+3] = fmaf(dv.w, S[q*4+3], kv.w * vj);
            }
            y += __shfl_xor_sync(0xffffffffu, y, 1);
            y += __shfl_xor_sync(0xffffffffu, y, 2);
            if (iq == 0) Y[ybase + (size_t)(tc + u) * CDIM + j] = y;
        }
        __syncthreads();
    }
}

/* ---------------- fused add + LayerNorm -> bf16 hi/lo ---------------------- */
__global__ void ln_kernel(const float* __restrict__ Y, const float* __restrict__ V2,
                          const float* __restrict__ gamma, const float* __restrict__ beta,
                          __nv_bfloat16* __restrict__ YH, __nv_bfloat16* __restrict__ YL)
{
    const int m = blockIdx.x;
    const int tid = threadIdx.x;
    const float4* y4 = (const float4*)(Y  + (size_t)m * CDIM);
    const float4* v4 = (const float4*)(V2 + (size_t)m * CDIM);
    float4 vals[2];
    float s = 0.f, s2 = 0.f;
#pragma unroll
    for (int u = 0; u < 2; u++) {
        float4 a = y4[tid + u*256], b = v4[tid + u*256];
        float4 v = make_float4(a.x+b.x, a.y+b.y, a.z+b.z, a.w+b.w);
        vals[u] = v;
        s  += v.x + v.y + v.z + v.w;
        s2 += v.x*v.x + v.y*v.y + v.z*v.z + v.w*v.w;
    }
#pragma unroll
    for (int o = 16; o; o >>= 1) {
        s  += __shfl_xor_sync(0xffffffffu, s,  o);
        s2 += __shfl_xor_sync(0xffffffffu, s2, o);
    }
    __shared__ float sh[2][8];
    const int w = tid >> 5, l = tid & 31;
    if (l == 0) { sh[0][w] = s; sh[1][w] = s2; }
    __syncthreads();
    s = 0.f; s2 = 0.f;
#pragma unroll
    for (int i = 0; i < 8; i++) { s += sh[0][i]; s2 += sh[1][i]; }
    const float mu   = s  * (1.f / CDIM);
    const float var  = s2 * (1.f / CDIM) - mu * mu;
    const float rstd = rsqrtf(var + 1e-5f);
    const float4* g4 = (const float4*)gamma;
    const float4* b4 = (const float4*)beta;
    __nv_bfloat162* yh2 = (__nv_bfloat162*)(YH + (size_t)m * CDIM);
    __nv_bfloat162* yl2 = (__nv_bfloat162*)(YL + (size_t)m * CDIM);
#pragma unroll
    for (int u = 0; u < 2; u++) {
        int c4 = tid + u*256;
        float4 g = g4[c4], bb = b4[c4], v = vals[u];
        float o0 = (v.x - mu) * rstd * g.x + bb.x;
        float o1 = (v.y - mu) * rstd * g.y + bb.y;
        float o2 = (v.z - mu) * rstd * g.z + bb.z;
        float o3 = (v.w - mu) * rstd * g.w + bb.w;
        __nv_bfloat16 h0 = __float2bfloat16(o0), h1 = __float2bfloat16(o1);
        __nv_bfloat16 h2 = __float2bfloat16(o2), h3 = __float2bfloat16(o3);
        __nv_bfloat162 hA; hA.x = h0; hA.y = h1;
        __nv_bfloat162 hB; hB.x = h2; hB.y = h3;
        __nv_bfloat162 lA; lA.x = __float2bfloat16(o0 - __bfloat162float(h0));
                           lA.y = __float2bfloat16(o1 - __bfloat162float(h1));
        __nv_bfloat162 lB; lB.x = __float2bfloat16(o2 - __bfloat162float(h2));
                           lB.y = __float2bfloat16(o3 - __bfloat162float(h3));
        yh2[2*c4]   = hA;  yh2[2*c4+1] = hB;
        yl2[2*c4]   = lA;  yl2[2*c4+1] = lB;
    }
}

/* ---------------- launch --------------------------------------------------- */
extern "C" void kernel_launch(void* const* d_in, const int* in_sizes, int n_in,
                              void* d_out, int out_size)
{
    const float* x_in     = (const float*)d_in[0];
    const float* shiftst  = (const float*)d_in[1];
    const float* wkvstate = (const float*)d_in[2];
    const float* tmr      = (const float*)d_in[3];
    const float* tmk      = (const float*)d_in[4];
    const float* tmv      = (const float*)d_in[5];
    const float* tmv2     = (const float*)d_in[6];
    const float* maa_w1   = (const float*)d_in[7];
    const float* maa_w2   = (const float*)d_in[8];
    const float* tmw      = (const float*)d_in[9];
    const float* ww1      = (const float*)d_in[10];
    const float* ww2      = (const float*)d_in[11];
    const float* tdecay   = (const float*)d_in[12];
    const float* dw1      = (const float*)d_in[13];
    const float* dw2      = (const float*)d_in[14];
    /* d_in[15] = time_faaaa: unused (u == 0 in this model) */
    const float* trec     = (const float*)d_in[16];
    const float* tkey     = (const float*)d_in[17];
    const float* value_w  = (const float*)d_in[18];
    const float* output_w = (const float*)d_in[19];
    const float* gamma    = (const float*)d_in[20];
    const float* beta     = (const float*)d_in[21];
    float* out = (float*)d_out;

    float *pX, *pXX1, *pXW1, *pT1, *pDEC, *pR, *pK, *pV, *pV2, *pY;
    __nv_bfloat16 *pXIH, *pXIL, *pYH, *pYL, *pXWH, *pXWL, *pVWH, *pVWL, *pOWH, *pOWL;
    __nv_bfloat16 *pW1TH, *pW1TL, *pDW1TH, *pDW1TL;
    cudaGetSymbolAddress((void**)&pX,   g_X);
    cudaGetSymbolAddress((void**)&pXX1, g_XX1);
    cudaGetSymbolAddress((void**)&pXW1, g_XW1);
    cudaGetSymbolAddress((void**)&pT1,  g_T1);
    cudaGetSymbolAddress((void**)&pDEC, g_DEC);
    cudaGetSymbolAddress((void**)&pR,   g_R);
    cudaGetSymbolAddress((void**)&pK,   g_K);
    cudaGetSymbolAddress((void**)&pV,   g_V);
    cudaGetSymbolAddress((void**)&pV2,  g_V2);
    cudaGetSymbolAddress((void**)&pY,   g_Y);
    cudaGetSymbolAddress((void**)&pXIH, g_XIH);
    cudaGetSymbolAddress((void**)&pXIL, g_XIL);
    cudaGetSymbolAddress((void**)&pYH,  g_YH);
    cudaGetSymbolAddress((void**)&pYL,  g_YL);
    cudaGetSymbolAddress((void**)&pXWH, g_XWH);
    cudaGetSymbolAddress((void**)&pXWL, g_XWL);
    cudaGetSymbolAddress((void**)&pVWH, g_VWH);
    cudaGetSymbolAddress((void**)&pVWL, g_VWL);
    cudaGetSymbolAddress((void**)&pOWH, g_OWH);
    cudaGetSymbolAddress((void**)&pOWL, g_OWL);
    cudaGetSymbolAddress((void**)&pW1TH,  g_W1TH);
    cudaGetSymbolAddress((void**)&pW1TL,  g_W1TL);
    cudaGetSymbolAddress((void**)&pDW1TH, g_DW1TH);
    cudaGetSymbolAddress((void**)&pDW1TL, g_DW1TL);

    const size_t SZ = (size_t)MTOT * CDIM;
    const int SPLIT_BLK_X  = (int)(SZ / 4 / 256);
    const int SPLIT_BLK_W  = (int)((size_t)CDIM * CDIM / 4 / 256);
    const int TS_BLKS = (CDIM * 128 + 255) / 256;
    const float* NUL = (const float*)0;
    __nv_bfloat16* NB = (__nv_bfloat16*)0;

    /* 0-2: bf16 hi/lo splits */
    split_kernel<<<SPLIT_BLK_X, 256>>>(x_in, pXIH, pXIL, (int)(SZ / 4));
    split_kernel<<<SPLIT_BLK_W, 256>>>(value_w,  pVWH, pVWL, (int)((size_t)CDIM*CDIM/4));
    split_kernel<<<SPLIT_BLK_W, 256>>>(output_w, pOWH, pOWL, (int)((size_t)CDIM*CDIM/4));
    /* 3-4: weight transpose-splits [K,N] -> [N,K] */
    tsplit_kernel<<<TS_BLKS, 256>>>(maa_w1, pW1TH, pW1TL, CDIM, 128);
    tsplit_kernel<<<TS_BLKS, 256>>>(dw1,    pDW1TH, pDW1TL, CDIM, 128);

    /* 5: XX1 = tanh(x_in @ maa_w1)  (skinny wmma, 128 blocks) */
    gemm_wmma3_skinny<<<dim3(1, MTOT/64), 256>>>(pXIH, pXIL, pW1TH, pW1TL, pXX1,
                                                 MTOT, CDIM);
    /* 6: X = x_in @ value_w^T */
    gemm_wmma3<<<dim3(CDIM/128, MTOT/128), 256>>>(pXIH, pXIL, pVWH, pVWL, pX,
                                                  MTOT, CDIM, CDIM);
    /* 7: XW1 = tanh(X @ w_w1) */
    gemm_nn<<<dim3(1, MTOT/64), 256>>>(pX, CDIM, 0, ww1, 32, pXW1, 32,
                                       MTOT, 32, CDIM, 1, NUL, NUL, NUL, NUL, NB, NB, NUL);
    /* 8: XW = X + dxprev*(time_maa_w + XW1 @ w_w2) -> bf16 hi/lo (epi=3) */
    gemm_nn<<<dim3(CDIM/128, MTOT/64), 256>>>(pXW1, 32, 0, ww2, CDIM, (float*)0, CDIM,
                                              MTOT, CDIM, 32, 3, NUL,
                                              pX, shiftst, tmw, pXWH, pXWL, NUL);
    /* 9: T1 = tanh(XW @ decay_w1)  (skinny wmma, 128 blocks) */
    gemm_wmma3_skinny<<<dim3(1, MTOT/64), 256>>>(pXWH, pXWL, pDW1TH, pDW1TL, pT1,
                                                 MTOT, CDIM);
    /* 10: DEC = exp(-exp(time_decay + T1 @ decay_w2)) */
    gemm_nn<<<dim3(CDIM/128, MTOT/64), 256>>>(pT1, 128, 0, dw2, CDIM, pDEC, CDIM,
                                              MTOT, CDIM, 128, 2, tdecay, NUL, NUL, NUL, NB, NB, NUL);
    /* 11-14: fused MIX GEMM + rkvv epilogues (MIX never materialized) */
    /* R: epi=5 */
    gemm_nn<<<dim3(CDIM/128, MTOT/64), 256>>>(pXX1, 128, 0, maa_w2, CDIM, pR, CDIM,
                                              MTOT, CDIM, 32, 5, tmr,
                                              pX, shiftst, trec, NB, NB, NUL);
    /* K: epi=6 */
    gemm_nn<<<dim3(CDIM/128, MTOT/64), 256>>>(pXX1, 128, 32, maa_w2 + (size_t)32*CDIM, CDIM, pK, CDIM,
                                              MTOT, CDIM, 32, 6, tmk,
                                              pX, shiftst, tkey, NB, NB, pDEC);
    /* V: epi=4 */
    gemm_nn<<<dim3(CDIM/128, MTOT/64), 256>>>(pXX1, 128, 64, maa_w2 + (size_t)64*CDIM, CDIM, pV, CDIM,
                                              MTOT, CDIM, 32, 4, tmv,
                                              pX, shiftst, NUL, NB, NB, NUL);
    /* V2: epi=4 */
    gemm_nn<<<dim3(CDIM/128, MTOT/64), 256>>>(pXX1, 128, 96, maa_w2 + (size_t)96*CDIM, CDIM, pV2, CDIM,
                                              MTOT, CDIM, 32, 4, tmv2,
                                              pX, shiftst, NUL, NB, NB, NUL);
    /* 15: WKV scan (8-step groups) */
    wkv_kernel<<<BATCH*NH, 256>>>(pR, pK, pV, pDEC, wkvstate, pY);
    /* 16: yn = LN(y + v2) -> bf16 hi/lo */
    ln_kernel<<<MTOT, 256>>>(pY, pV2, gamma, beta, pYH, pYL);
    /* 17: out = yn @ output_w^T */
    gemm_wmma3<<<dim3(CDIM/128, MTOT/128), 256>>>(pYH, pYL, pOWH, pOWL, out,
                                                  MTOT, CDIM, CDIM);
}

// round 16
// speedup vs baseline: 1.1227x; 1.0287x over previous
#include <cuda_runtime.h>
#include <cuda_bf16.h>
#include <mma.h>
#include <math.h>
#include <stdint.h>

using namespace nvcuda;

#define BATCH 4
#define TLEN  2048
#define CDIM  2048
#define HS    64
#define NH    32
#define MTOT  (BATCH*TLEN)   /* 8192 */

/* ---------------- scratch (static device allocations; no cudaMalloc) ------- */
__device__ float g_X  [(size_t)MTOT*CDIM];
__device__ float g_XX1[(size_t)MTOT*128];
__device__ float g_XW1[(size_t)MTOT*32];
__device__ float g_T1 [(size_t)MTOT*128];
__device__ float g_DEC[(size_t)MTOT*CDIM];
__device__ float g_R  [(size_t)MTOT*CDIM];
__device__ float g_K  [(size_t)MTOT*CDIM];
__device__ float g_V  [(size_t)MTOT*CDIM];
__device__ float g_V2 [(size_t)MTOT*CDIM];
__device__ float g_Y  [(size_t)MTOT*CDIM];
/* bf16 hi/lo splits */
__device__ __nv_bfloat16 g_XIH[(size_t)MTOT*CDIM];
__device__ __nv_bfloat16 g_XIL[(size_t)MTOT*CDIM];
__device__ __nv_bfloat16 g_XH [(size_t)MTOT*CDIM];
__device__ __nv_bfloat16 g_XL [(size_t)MTOT*CDIM];
__device__ __nv_bfloat16 g_YH [(size_t)MTOT*CDIM];
__device__ __nv_bfloat16 g_YL [(size_t)MTOT*CDIM];
__device__ __nv_bfloat16 g_XWH[(size_t)MTOT*CDIM];
__device__ __nv_bfloat16 g_XWL[(size_t)MTOT*CDIM];
__device__ __nv_bfloat16 g_VWH[(size_t)CDIM*CDIM];
__device__ __nv_bfloat16 g_VWL[(size_t)CDIM*CDIM];
__device__ __nv_bfloat16 g_OWH[(size_t)CDIM*CDIM];
__device__ __nv_bfloat16 g_OWL[(size_t)CDIM*CDIM];
/* transposed weight splits: [N, K] layout */
__device__ __nv_bfloat16 g_W1TH[(size_t)128*CDIM];
__device__ __nv_bfloat16 g_W1TL[(size_t)128*CDIM];
__device__ __nv_bfloat16 g_DW1TH[(size_t)128*CDIM];
__device__ __nv_bfloat16 g_DW1TL[(size_t)128*CDIM];
__device__ __nv_bfloat16 g_WW1TH[(size_t)32*CDIM];
__device__ __nv_bfloat16 g_WW1TL[(size_t)32*CDIM];

#define WLD 40   /* smem row pitch in bf16 */

/* ================= bf16-split WMMA GEMM (NT) — R10-exact core ============== */
__global__ __launch_bounds__(256)
void gemm_wmma3(const __nv_bfloat16* __restrict__ AH, const __nv_bfloat16* __restrict__ AL,
                const __nv_bfloat16* __restrict__ BH, const __nv_bfloat16* __restrict__ BL,
                float* __restrict__ C, int M, int N, int K)
{
    __shared__ __nv_bfloat16 AsH[128][WLD];
    __shared__ __nv_bfloat16 AsL[128][WLD];
    __shared__ __nv_bfloat16 BsH[128][WLD];
    __shared__ __nv_bfloat16 BsL[128][WLD];

    const int tid = threadIdx.x;
    const int wid = tid >> 5;
    const int wm = wid & 1;
    const int wn = wid >> 1;
    const int bm = blockIdx.y * 128;
    const int bn = blockIdx.x * 128;

    wmma::fragment<wmma::accumulator, 16, 16, 16, float> acc[4][2];
#pragma unroll
    for (int i = 0; i < 4; i++)
#pragma unroll
        for (int j = 0; j < 2; j++) wmma::fill_fragment(acc[i][j], 0.f);

    int lrow[2], lc8[2];
#pragma unroll
    for (int u = 0; u < 2; u++) {
        int i = tid + (u << 8);
        lrow[u] = i >> 2;
        lc8[u]  = (i & 3) << 3;
    }

    uint4 pAH[2], pAL[2], pBH[2], pBL[2];
#pragma unroll
    for (int u = 0; u < 2; u++) {
        size_t sa = (size_t)(bm + lrow[u]) * K + lc8[u];
        size_t sb = (size_t)(bn + lrow[u]) * K + lc8[u];
        pAH[u] = *(const uint4*)(AH + sa);
        pAL[u] = *(const uint4*)(AL + sa);
        pBH[u] = *(const uint4*)(BH + sb);
        pBL[u] = *(const uint4*)(BL + sb);
    }

    const int nchunks = K >> 5;
    for (int c = 0; c < nchunks; c++) {
#pragma unroll
        for (int u = 0; u < 2; u++) {
            *(uint4*)&AsH[lrow[u]][lc8[u]] = pAH[u];
            *(uint4*)&AsL[lrow[u]][lc8[u]] = pAL[u];
            *(uint4*)&BsH[lrow[u]][lc8[u]] = pBH[u];
            *(uint4*)&BsL[lrow[u]][lc8[u]] = pBL[u];
        }
        __syncthreads();

        if (c + 1 < nchunks) {
            const int k0 = (c + 1) << 5;
#pragma unroll
            for (int u = 0; u < 2; u++) {
                size_t sa = (size_t)(bm + lrow[u]) * K + k0 + lc8[u];
                size_t sb = (size_t)(bn + lrow[u]) * K + k0 + lc8[u];
                pAH[u] = *(const uint4*)(AH + sa);
                pAL[u] = *(const uint4*)(AL + sa);
                pBH[u] = *(const uint4*)(BH + sb);
                pBL[u] = *(const uint4*)(BL + sb);
            }
        }

#pragma unroll
        for (int ks = 0; ks < 2; ks++) {
            wmma::fragment<wmma::matrix_b, 16, 16, 16, __nv_bfloat16, wmma::col_major> bh[2], bl[2];
#pragma unroll
            for (int j = 0; j < 2; j++) {
                wmma::load_matrix_sync(bh[j], &BsH[wn*32 + j*16][ks*16], WLD);
                wmma::load_matrix_sync(bl[j], &BsL[wn*32 + j*16][ks*16], WLD);
            }
#pragma unroll
            for (int i = 0; i < 4; i++) {
                wmma::fragment<wmma::matrix_a, 16, 16, 16, __nv_bfloat16, wmma::row_major> ah, al;
                wmma::load_matrix_sync(ah, &AsH[wm*64 + i*16][ks*16], WLD);
                wmma::load_matrix_sync(al, &AsL[wm*64 + i*16][ks*16], WLD);
#pragma unroll
                for (int j = 0; j < 2; j++) {
                    wmma::mma_sync(acc[i][j], ah, bh[j], acc[i][j]);
                    wmma::mma_sync(acc[i][j], ah, bl[j], acc[i][j]);
                    wmma::mma_sync(acc[i][j], al, bh[j], acc[i][j]);
                }
            }
        }
        __syncthreads();
    }

#pragma unroll
    for (int i = 0; i < 4; i++)
#pragma unroll
        for (int j = 0; j < 2; j++)
            wmma::store_matrix_sync(&C[(size_t)(bm + wm*64 + i*16) * N + bn + wn*32 + j*16],
                                    acc[i][j], N, wmma::mem_row_major);
}

/* ================= skinny variant: BM=64, BN=128, tanh epilogue ============ */
__global__ __launch_bounds__(256)
void gemm_wmma3_skinny(const __nv_bfloat16* __restrict__ AH, const __nv_bfloat16* __restrict__ AL,
                       const __nv_bfloat16* __restrict__ BH, const __nv_bfloat16* __restrict__ BL,
                       float* __restrict__ C, int M, int K)
{
    __shared__ __nv_bfloat16 AsH[64][WLD];
    __shared__ __nv_bfloat16 AsL[64][WLD];
    __shared__ __nv_bfloat16 BsH[128][WLD];
    __shared__ __nv_bfloat16 BsL[128][WLD];

    const int tid = threadIdx.x;
    const int wid = tid >> 5;
    const int wm = wid & 1;
    const int wn = wid >> 1;
    const int bm = blockIdx.y * 64;

    wmma::fragment<wmma::accumulator, 16, 16, 16, float> acc[2][2];
#pragma unroll
    for (int i = 0; i < 2; i++)
#pragma unroll
        for (int j = 0; j < 2; j++) wmma::fill_fragment(acc[i][j], 0.f);

    const int larA = tid >> 2, lcA = (tid & 3) << 3;
    int lrB[2], lcB[2];
#pragma unroll
    for (int u = 0; u < 2; u++) {
        int i = tid + (u << 8);
        lrB[u] = i >> 2;
        lcB[u] = (i & 3) << 3;
    }

    uint4 pAH, pAL, pBH[2], pBL[2];
    {
        size_t sa = (size_t)(bm + larA) * K + lcA;
        pAH = *(const uint4*)(AH + sa);
        pAL = *(const uint4*)(AL + sa);
#pragma unroll
        for (int u = 0; u < 2; u++) {
            size_t sb = (size_t)lrB[u] * K + lcB[u];
            pBH[u] = *(const uint4*)(BH + sb);
            pBL[u] = *(const uint4*)(BL + sb);
        }
    }

    const int nchunks = K >> 5;
    for (int c = 0; c < nchunks; c++) {
        *(uint4*)&AsH[larA][lcA] = pAH;
        *(uint4*)&AsL[larA][lcA] = pAL;
#pragma unroll
        for (int u = 0; u < 2; u++) {
            *(uint4*)&BsH[lrB[u]][lcB[u]] = pBH[u];
            *(uint4*)&BsL[lrB[u]][lcB[u]] = pBL[u];
        }
        __syncthreads();

        if (c + 1 < nchunks) {
            const int k0 = (c + 1) << 5;
            size_t sa = (size_t)(bm + larA) * K + k0 + lcA;
            pAH = *(const uint4*)(AH + sa);
            pAL = *(const uint4*)(AL + sa);
#pragma unroll
            for (int u = 0; u < 2; u++) {
                size_t sb = (size_t)lrB[u] * K + k0 + lcB[u];
                pBH[u] = *(const uint4*)(BH + sb);
                pBL[u] = *(const uint4*)(BL + sb);
            }
        }

#pragma unroll
        for (int ks = 0; ks < 2; ks++) {
            wmma::fragment<wmma::matrix_b, 16, 16, 16, __nv_bfloat16, wmma::col_major> bh[2], bl[2];
#pragma unroll
            for (int j = 0; j < 2; j++) {
                wmma::load_matrix_sync(bh[j], &BsH[wn*32 + j*16][ks*16], WLD);
                wmma::load_matrix_sync(bl[j], &BsL[wn*32 + j*16][ks*16], WLD);
            }
#pragma unroll
            for (int i = 0; i < 2; i++) {
                wmma::fragment<wmma::matrix_a, 16, 16, 16, __nv_bfloat16, wmma::row_major> ah, al;
                wmma::load_matrix_sync(ah, &AsH[wm*32 + i*16][ks*16], WLD);
                wmma::load_matrix_sync(al, &AsL[wm*32 + i*16][ks*16], WLD);
#pragma unroll
                for (int j = 0; j < 2; j++) {
                    wmma::mma_sync(acc[i][j], ah, bh[j], acc[i][j]);
                    wmma::mma_sync(acc[i][j], ah, bl[j], acc[i][j]);
                    wmma::mma_sync(acc[i][j], al, bh[j], acc[i][j]);
                }
            }
        }
        __syncthreads();
    }

#pragma unroll
    for (int i = 0; i < 2; i++)
#pragma unroll
        for (int j = 0; j < 2; j++) {
            for (int e = 0; e < acc[i][j].num_elements; e++)
                acc[i][j].x[e] = tanhf(acc[i][j].x[e]);
            wmma::store_matrix_sync(&C[(size_t)(bm + wm*32 + i*16) * 128 + wn*32 + j*16],
                                    acc[i][j], 128, wmma::mem_row_major);
        }
}

/* ================= N=32 variant: BM=64, BN=32, tanh epilogue (XW1) =========
   8 warps in 4x2; one 16x16 acc per warp. Load-bound: reads AH/AL once.   */
__global__ __launch_bounds__(256)
void gemm_wmma3_n32(const __nv_bfloat16* __restrict__ AH, const __nv_bfloat16* __restrict__ AL,
                    const __nv_bfloat16* __restrict__ BH, const __nv_bfloat16* __restrict__ BL,
                    float* __restrict__ C, int M, int K)
{
    __shared__ __nv_bfloat16 AsH[64][WLD];
    __shared__ __nv_bfloat16 AsL[64][WLD];
    __shared__ __nv_bfloat16 BsH[32][WLD];
    __shared__ __nv_bfloat16 BsL[32][WLD];

    const int tid = threadIdx.x;
    const int wid = tid >> 5;
    const int wm = wid >> 1;       /* 0..3 -> 16-row slab */
    const int wn = wid & 1;        /* 0..1 -> 16-col slab */
    const int bm = blockIdx.y * 64;

    wmma::fragment<wmma::accumulator, 16, 16, 16, float> acc;
    wmma::fill_fragment(acc, 0.f);

    const int larA = tid >> 2, lcA = (tid & 3) << 3;      /* 64 rows x 4 uint4 */
    const int lrB = tid >> 2, lcB = (tid & 3) << 3;       /* tid<128: 32 rows  */
    const bool bAct = (tid < 128);

    uint4 pAH, pAL, pBH, pBL;
    {
        size_t sa = (size_t)(bm + larA) * K + lcA;
        pAH = *(const uint4*)(AH + sa);
        pAL = *(const uint4*)(AL + sa);
        if (bAct) {
            size_t sb = (size_t)lrB * K + lcB;
            pBH = *(const uint4*)(BH + sb);
            pBL = *(const uint4*)(BL + sb);
        }
    }

    const int nchunks = K >> 5;
    for (int c = 0; c < nchunks; c++) {
        *(uint4*)&AsH[larA][lcA] = pAH;
        *(uint4*)&AsL[larA][lcA] = pAL;
        if (bAct) {
            *(uint4*)&BsH[lrB][lcB] = pBH;
            *(uint4*)&BsL[lrB][lcB] = pBL;
        }
        __syncthreads();

        if (c + 1 < nchunks) {
            const int k0 = (c + 1) << 5;
            size_t sa = (size_t)(bm + larA) * K + k0 + lcA;
            pAH = *(const uint4*)(AH + sa);
            pAL = *(const uint4*)(AL + sa);
            if (bAct) {
                size_t sb = (size_t)lrB * K + k0 + lcB;
                pBH = *(const uint4*)(BH + sb);
                pBL = *(const uint4*)(BL + sb);
            }
        }

#pragma unroll
        for (int ks = 0; ks < 2; ks++) {
            wmma::fragment<wmma::matrix_b, 16, 16, 16, __nv_bfloat16, wmma::col_major> bh, bl;
            wmma::load_matrix_sync(bh, &BsH[wn*16][ks*16], WLD);
            wmma::load_matrix_sync(bl, &BsL[wn*16][ks*16], WLD);
            wmma::fragment<wmma::matrix_a, 16, 16, 16, __nv_bfloat16, wmma::row_major> ah, al;
            wmma::load_matrix_sync(ah, &AsH[wm*16][ks*16], WLD);
            wmma::load_matrix_sync(al, &AsL[wm*16][ks*16], WLD);
            wmma::mma_sync(acc, ah, bh, acc);
            wmma::mma_sync(acc, ah, bl, acc);
            wmma::mma_sync(acc, al, bh, acc);
        }
        __syncthreads();
    }

    for (int e = 0; e < acc.num_elements; e++)
        acc.x[e] = tanhf(acc.x[e]);
    wmma::store_matrix_sync(&C[(size_t)(bm + wm*16) * 32 + wn*16],
                            acc, 32, wmma::mem_row_major);
}

/* ---------------- fp32 -> bf16 hi/lo split --------------------------------- */
__global__ void split_kernel(const float* __restrict__ in,
                             __nv_bfloat16* __restrict__ hi,
                             __nv_bfloat16* __restrict__ lo, int n4)
{
    int i = blockIdx.x * 256 + threadIdx.x;
    if (i >= n4) return;
    float4 x = ((const float4*)in)[i];
    __nv_bfloat16 h0 = __float2bfloat16(x.x), h1 = __float2bfloat16(x.y);
    __nv_bfloat16 h2 = __float2bfloat16(x.z), h3 = __float2bfloat16(x.w);
    __nv_bfloat162 hA; hA.x = h0; hA.y = h1;
    __nv_bfloat162 hB; hB.x = h2; hB.y = h3;
    __nv_bfloat162 lA; lA.x = __float2bfloat16(x.x - __bfloat162float(h0));
                       lA.y = __float2bfloat16(x.y - __bfloat162float(h1));
    __nv_bfloat162 lB; lB.x = __float2bfloat16(x.z - __bfloat162float(h2));
                       lB.y = __float2bfloat16(x.w - __bfloat162float(h3));
    ((__nv_bfloat162*)hi)[2*i]   = hA;
    ((__nv_bfloat162*)hi)[2*i+1] = hB;
    ((__nv_bfloat162*)lo)[2*i]   = lA;
    ((__nv_bfloat162*)lo)[2*i+1] = lB;
}

/* ---------------- [K,N] fp32 -> [N,K] bf16 hi/lo transpose-split ----------- */
__global__ void tsplit_kernel(const float* __restrict__ in,
                              __nv_bfloat16* __restrict__ hiT,
                              __nv_bfloat16* __restrict__ loT, int K, int N)
{
    int idx = blockIdx.x * 256 + threadIdx.x;
    if (idx >= K * N) return;
    int k = idx / N, n = idx % N;
    float v = in[idx];
    __nv_bfloat16 h = __float2bfloat16(v);
    hiT[(size_t)n * K + k] = h;
    loT[(size_t)n * K + k] = __float2bfloat16(v - __bfloat162float(h));
}

/* ---------------- generic NN GEMM: C[m,n] = f(sum_k A[m,lda..]*B[k,n]) ------
   epi: 0=none, 1=tanh, 2=exp(-exp(bias[n]+acc)),
        3=XW fusion -> bf16 hi/lo CH/CL,
        4=x + dx*(bias[n]+acc), 5=...*tw[n], 6=...*tw[n]*(1-dec)           */
__global__ __launch_bounds__(256, 2)
void gemm_nn(const float* __restrict__ A, int lda, int aoff,
             const float* __restrict__ B, int ldb,
             float* __restrict__ C, int ldc,
             int M, int N, int K, int epi, const float* __restrict__ bias,
             const float* __restrict__ Xf, const float* __restrict__ shf,
             const float* __restrict__ tw,
             __nv_bfloat16* __restrict__ CH, __nv_bfloat16* __restrict__ CL,
             const float* __restrict__ decp)
{
    __shared__ float As[64][36];
    __shared__ float Bs[32][128];
    const int tid = threadIdx.x;
    const int bm = blockIdx.y * 64;
    const int bn = blockIdx.x * 128;
    const int cx = tid & 31;
    const int rg = tid >> 5;

    float4 acc[8];
#pragma unroll
    for (int r = 0; r < 8; r++) acc[r] = make_float4(0.f,0.f,0.f,0.f);

    for (int k0 = 0; k0 < K; k0 += 32) {
#pragma unroll
        for (int u = 0; u < 2; u++) {
            int i = tid + 256*u;
            int r = i >> 3, kq = (i & 7) << 2;
            float4 v = *(const float4*)&A[(size_t)(bm + r) * lda + aoff + k0 + kq];
            *(float4*)&As[r][kq] = v;
        }
#pragma unroll
        for (int u = 0; u < 4; u++) {
            int i = tid + 256*u;
            int kr = i >> 5, nq = (i & 31) << 2;
            float4 v = make_float4(0.f,0.f,0.f,0.f);
            if (bn + nq < N)
                v = *(const float4*)&B[(size_t)(k0 + kr) * ldb + bn + nq];
            *(float4*)&Bs[kr][nq] = v;
        }
        __syncthreads();
#pragma unroll 8
        for (int k = 0; k < 32; k++) {
            float4 bv = *(const float4*)&Bs[k][cx << 2];
#pragma unroll
            for (int r = 0; r < 8; r++) {
                float a = As[rg*8 + r][k];
                acc[r].x = fmaf(a, bv.x, acc[r].x);
                acc[r].y = fmaf(a, bv.y, acc[r].y);
                acc[r].z = fmaf(a, bv.z, acc[r].z);
                acc[r].w = fmaf(a, bv.w, acc[r].w);
            }
        }
        __syncthreads();
    }
    const int n = bn + (cx << 2);
    if (n < N) {
#pragma unroll
        for (int r = 0; r < 8; r++) {
            float4 o = acc[r];
            const int m = bm + rg*8 + r;
            if (epi == 1) {
                o.x = tanhf(o.x); o.y = tanhf(o.y); o.z = tanhf(o.z); o.w = tanhf(o.w);
            } else if (epi == 2) {
                o.x = expf(-expf(bias[n+0] + o.x));
                o.y = expf(-expf(bias[n+1] + o.y));
                o.z = expf(-expf(bias[n+2] + o.z));
                o.w = expf(-expf(bias[n+3] + o.w));
            } else if (epi == 3) {
                const int t = m & (TLEN-1), b = m >> 11;
                float4 x  = *(const float4*)&Xf[(size_t)m * CDIM + n];
                float4 xp = (t == 0)
                    ? *(const float4*)&shf[(size_t)b * CDIM + n]
                    : *(const float4*)&Xf[(size_t)(m-1) * CDIM + n];
                float4 w  = *(const float4*)&tw[n];
                o.x = x.x + (xp.x - x.x) * (w.x + o.x);
                o.y = x.y + (xp.y - x.y) * (w.y + o.y);
                o.z = x.z + (xp.z - x.z) * (w.z + o.z);
                o.w = x.w + (xp.w - x.w) * (w.w + o.w);
                __nv_bfloat16 h0 = __float2bfloat16(o.x), h1 = __float2bfloat16(o.y);
                __nv_bfloat16 h2 = __float2bfloat16(o.z), h3 = __float2bfloat16(o.w);
                __nv_bfloat162 hA; hA.x = h0; hA.y = h1;
                __nv_bfloat162 hB; hB.x = h2; hB.y = h3;
                __nv_bfloat162 lA; lA.x = __float2bfloat16(o.x - __bfloat162float(h0));
                                   lA.y = __float2bfloat16(o.y - __bfloat162float(h1));
                __nv_bfloat162 lB; lB.x = __float2bfloat16(o.z - __bfloat162float(h2));
                                   lB.y = __float2bfloat16(o.w - __bfloat162float(h3));
                ((__nv_bfloat162*)&CH[(size_t)m * ldc + n])[0] = hA;
                ((__nv_bfloat162*)&CH[(size_t)m * ldc + n])[1] = hB;
                ((__nv_bfloat162*)&CL[(size_t)m * ldc + n])[0] = lA;
                ((__nv_bfloat162*)&CL[(size_t)m * ldc + n])[1] = lB;
                continue;
            } else if (epi >= 4) {
                const int t = m & (TLEN-1), b = m >> 11;
                float4 x  = *(const float4*)&Xf[(size_t)m * CDIM + n];
                float4 xp = (t == 0)
                    ? *(const float4*)&shf[(size_t)b * CDIM + n]
                    : *(const float4*)&Xf[(size_t)(m-1) * CDIM + n];
                float4 cb = *(const float4*)&bias[n];
                o.x = x.x + (xp.x - x.x) * (cb.x + o.x);
                o.y = x.y + (xp.y - x.y) * (cb.y + o.y);
                o.z = x.z + (xp.z - x.z) * (cb.z + o.z);
                o.w = x.w + (xp.w - x.w) * (cb.w + o.w);
                if (epi >= 5) {
                    float4 sc = *(const float4*)&tw[n];
                    o.x *= sc.x; o.y *= sc.y; o.z *= sc.z; o.w *= sc.w;
                }
                if (epi == 6) {
                    float4 d = *(const float4*)&decp[(size_t)m * CDIM + n];
                    o.x *= (1.f - d.x); o.y *= (1.f - d.y);
                    o.z *= (1.f - d.z); o.w *= (1.f - d.w);
                }
            }
            *(float4*)&C[(size_t)m * ldc + n] = o;
        }
    }
}

/* ---------------- WKV sequential scan, 8-step groups ----------------------- */
#define GSTEP 8
__global__ __launch_bounds__(256, 1)
void wkv_kernel(const float* __restrict__ Rp, const float* __restrict__ Kp,
                const float* __restrict__ Vp, const float* __restrict__ Dp,
                const float* __restrict__ S0, float* __restrict__ Y)
{
    const int bh = blockIdx.x;
    const int b = bh >> 5, h = bh & (NH-1);
    const int tid = threadIdx.x;
    const int j = tid >> 2, iq = tid & 3;

    float S[16];
    const float* s0p = S0 + (size_t)bh * HS * HS;
#pragma unroll
    for (int ii = 0; ii < 16; ii++) S[ii] = s0p[((iq << 4) + ii) * HS + j];

    __shared__ float sbuf[GSTEP][4][64];

    const int grp = tid >> 6, lane = tid & 63;
    const size_t base = ((size_t)b * TLEN) * CDIM + h * HS;
    const float* myp =
        ((grp == 0) ? Rp : (grp == 1) ? Kp : (grp == 2) ? Dp : Vp) + base + lane;

    float pre[GSTEP];
#pragma unroll
    for (int u = 0; u < GSTEP; u++) pre[u] = myp[(size_t)u * CDIM];

    const size_t ybase = base;
    for (int tc = 0; tc < TLEN; tc += GSTEP) {
#pragma unroll
        for (int u = 0; u < GSTEP; u++) sbuf[u][grp][lane] = pre[u];
        __syncthreads();
        if (tc + GSTEP < TLEN) {
#pragma unroll
            for (int u = 0; u < GSTEP; u++)
                pre[u] = myp[(size_t)(tc + GSTEP + u) * CDIM];
        }
#pragma unroll
        for (int u = 0; u < GSTEP; u++) {
            const float4* r4 = (const float4*)sbuf[u][0];
            const float4* k4 = (const float4*)sbuf[u][1];
            const float4* d4 = (const float4*)sbuf[u][2];
            const float vj = sbuf[u][3][j];
            float y = 0.f;
#pragma unroll
            for (int q = 0; q < 4; q++) {
                float4 rv = r4[iq*4 + q];
                y = fmaf(rv.x, S[q*4+0], y);
                y = fmaf(rv.y, S[q*4+1], y);
                y = fmaf(rv.z, S[q*4+2], y);
                y = fmaf(rv.w, S[q*4+3], y);
            }
#pragma unroll
            for (int q = 0; q < 4; q++) {
                float4 dv = d4[iq*4 + q];
                float4 kv = k4[iq*4 + q];
                S[q*4+0] = fmaf(dv.x, S[q*4+0], kv.x * vj);
                S[q*4+1] = fmaf(dv.y, S[q*4+1], kv.y * vj);
                S[q*4+2] = fmaf(dv.z, S[q*4+2], kv.z * vj);
                S[q*4+3] = fmaf(dv.w, S[q*4+3], kv.w * vj);
            }
            y += __shfl_xor_sync(0xffffffffu, y, 1);
            y += __shfl_xor_sync(0xffffffffu, y, 2);
            if (iq == 0) Y[ybase + (size_t)(tc + u) * CDIM + j] = y;
        }
        __syncthreads();
    }
}

/* ---------------- fused add + LayerNorm -> bf16 hi/lo ---------------------- */
__global__ void ln_kernel(const float* __restrict__ Y, const float* __restrict__ V2,
                          const float* __restrict__ gamma, const float* __restrict__ beta,
                          __nv_bfloat16* __restrict__ YH, __nv_bfloat16* __restrict__ YL)
{
    const int m = blockIdx.x;
    const int tid = threadIdx.x;
    const float4* y4 = (const float4*)(Y  + (size_t)m * CDIM);
    const float4* v4 = (const float4*)(V2 + (size_t)m * CDIM);
    float4 vals[2];
    float s = 0.f, s2 = 0.f;
#pragma unroll
    for (int u = 0; u < 2; u++) {
        float4 a = y4[tid + u*256], b = v4[tid + u*256];
        float4 v = make_float4(a.x+b.x, a.y+b.y, a.z+b.z, a.w+b.w);
        vals[u] = v;
        s  += v.x + v.y + v.z + v.w;
        s2 += v.x*v.x + v.y*v.y + v.z*v.z + v.w*v.w;
    }
#pragma unroll
    for (int o = 16; o; o >>= 1) {
        s  += __shfl_xor_sync(0xffffffffu, s,  o);
        s2 += __shfl_xor_sync(0xffffffffu, s2, o);
    }
    __shared__ float sh[2][8];
    const int w = tid >> 5, l = tid & 31;
    if (l == 0) { sh[0][w] = s; sh[1][w] = s2; }
    __syncthreads();
    s = 0.f; s2 = 0.f;
#pragma unroll
    for (int i = 0; i < 8; i++) { s += sh[0][i]; s2 += sh[1][i]; }
    const float mu   = s  * (1.f / CDIM);
    const float var  = s2 * (1.f / CDIM) - mu * mu;
    const float rstd = rsqrtf(var + 1e-5f);
    const float4* g4 = (const float4*)gamma;
    const float4* b4 = (const float4*)beta;
    __nv_bfloat162* yh2 = (__nv_bfloat162*)(YH + (size_t)m * CDIM);
    __nv_bfloat162* yl2 = (__nv_bfloat162*)(YL + (size_t)m * CDIM);
#pragma unroll
    for (int u = 0; u < 2; u++) {
        int c4 = tid + u*256;
        float4 g = g4[c4], bb = b4[c4], v = vals[u];
        float o0 = (v.x - mu) * rstd * g.x + bb.x;
        float o1 = (v.y - mu) * rstd * g.y + bb.y;
        float o2 = (v.z - mu) * rstd * g.z + bb.z;
        float o3 = (v.w - mu) * rstd * g.w + bb.w;
        __nv_bfloat16 h0 = __float2bfloat16(o0), h1 = __float2bfloat16(o1);
        __nv_bfloat16 h2 = __float2bfloat16(o2), h3 = __float2bfloat16(o3);
        __nv_bfloat162 hA; hA.x = h0; hA.y = h1;
        __nv_bfloat162 hB; hB.x = h2; hB.y = h3;
        __nv_bfloat162 lA; lA.x = __float2bfloat16(o0 - __bfloat162float(h0));
                           lA.y = __float2bfloat16(o1 - __bfloat162float(h1));
        __nv_bfloat162 lB; lB.x = __float2bfloat16(o2 - __bfloat162float(h2));
                           lB.y = __float2bfloat16(o3 - __bfloat162float(h3));
        yh2[2*c4]   = hA;  yh2[2*c4+1] = hB;
        yl2[2*c4]   = lA;  yl2[2*c4+1] = lB;
    }
}

/* ---------------- launch --------------------------------------------------- */
extern "C" void kernel_launch(void* const* d_in, const int* in_sizes, int n_in,
                              void* d_out, int out_size)
{
    const float* x_in     = (const float*)d_in[0];
    const float* shiftst  = (const float*)d_in[1];
    const float* wkvstate = (const float*)d_in[2];
    const float* tmr      = (const float*)d_in[3];
    const float* tmk      = (const float*)d_in[4];
    const float* tmv      = (const float*)d_in[5];
    const float* tmv2     = (const float*)d_in[6];
    const float* maa_w1   = (const float*)d_in[7];
    const float* maa_w2   = (const float*)d_in[8];
    const float* tmw      = (const float*)d_in[9];
    const float* ww1      = (const float*)d_in[10];
    const float* ww2      = (const float*)d_in[11];
    const float* tdecay   = (const float*)d_in[12];
    const float* dw1      = (const float*)d_in[13];
    const float* dw2      = (const float*)d_in[14];
    /* d_in[15] = time_faaaa: unused (u == 0 in this model) */
    const float* trec     = (const float*)d_in[16];
    const float* tkey     = (const float*)d_in[17];
    const float* value_w  = (const float*)d_in[18];
    const float* output_w = (const float*)d_in[19];
    const float* gamma    = (const float*)d_in[20];
    const float* beta     = (const float*)d_in[21];
    float* out = (float*)d_out;

    float *pX, *pXX1, *pXW1, *pT1, *pDEC, *pR, *pK, *pV, *pV2, *pY;
    __nv_bfloat16 *pXIH, *pXIL, *pXH, *pXL, *pYH, *pYL, *pXWH, *pXWL;
    __nv_bfloat16 *pVWH, *pVWL, *pOWH, *pOWL;
    __nv_bfloat16 *pW1TH, *pW1TL, *pDW1TH, *pDW1TL, *pWW1TH, *pWW1TL;
    cudaGetSymbolAddress((void**)&pX,   g_X);
    cudaGetSymbolAddress((void**)&pXX1, g_XX1);
    cudaGetSymbolAddress((void**)&pXW1, g_XW1);
    cudaGetSymbolAddress((void**)&pT1,  g_T1);
    cudaGetSymbolAddress((void**)&pDEC, g_DEC);
    cudaGetSymbolAddress((void**)&pR,   g_R);
    cudaGetSymbolAddress((void**)&pK,   g_K);
    cudaGetSymbolAddress((void**)&pV,   g_V);
    cudaGetSymbolAddress((void**)&pV2,  g_V2);
    cudaGetSymbolAddress((void**)&pY,   g_Y);
    cudaGetSymbolAddress((void**)&pXIH, g_XIH);
    cudaGetSymbolAddress((void**)&pXIL, g_XIL);
    cudaGetSymbolAddress((void**)&pXH,  g_XH);
    cudaGetSymbolAddress((void**)&pXL,  g_XL);
    cudaGetSymbolAddress((void**)&pYH,  g_YH);
    cudaGetSymbolAddress((void**)&pYL,  g_YL);
    cudaGetSymbolAddress((void**)&pXWH, g_XWH);
    cudaGetSymbolAddress((void**)&pXWL, g_XWL);
    cudaGetSymbolAddress((void**)&pVWH, g_VWH);
    cudaGetSymbolAddress((void**)&pVWL, g_VWL);
    cudaGetSymbolAddress((void**)&pOWH, g_OWH);
    cudaGetSymbolAddress((void**)&pOWL, g_OWL);
    cudaGetSymbolAddress((void**)&pW1TH,  g_W1TH);
    cudaGetSymbolAddress((void**)&pW1TL,  g_W1TL);
    cudaGetSymbolAddress((void**)&pDW1TH, g_DW1TH);
    cudaGetSymbolAddress((void**)&pDW1TL, g_DW1TL);
    cudaGetSymbolAddress((void**)&pWW1TH, g_WW1TH);
    cudaGetSymbolAddress((void**)&pWW1TL, g_WW1TL);

    const size_t SZ = (size_t)MTOT * CDIM;
    const int SPLIT_BLK_X  = (int)(SZ / 4 / 256);
    const int SPLIT_BLK_W  = (int)((size_t)CDIM * CDIM / 4 / 256);
    const int TS_BLKS128 = (CDIM * 128 + 255) / 256;
    const int TS_BLKS32  = (CDIM * 32 + 255) / 256;
    const float* NUL = (const float*)0;
    __nv_bfloat16* NB = (__nv_bfloat16*)0;

    /* splits */
    split_kernel<<<SPLIT_BLK_X, 256>>>(x_in, pXIH, pXIL, (int)(SZ / 4));
    split_kernel<<<SPLIT_BLK_W, 256>>>(value_w,  pVWH, pVWL, (int)((size_t)CDIM*CDIM/4));
    split_kernel<<<SPLIT_BLK_W, 256>>>(output_w, pOWH, pOWL, (int)((size_t)CDIM*CDIM/4));
    tsplit_kernel<<<TS_BLKS128, 256>>>(maa_w1, pW1TH, pW1TL, CDIM, 128);
    tsplit_kernel<<<TS_BLKS128, 256>>>(dw1,    pDW1TH, pDW1TL, CDIM, 128);
    tsplit_kernel<<<TS_BLKS32,  256>>>(ww1,    pWW1TH, pWW1TL, CDIM, 32);

    /* XX1 = tanh(x_in @ maa_w1)  (skinny wmma) */
    gemm_wmma3_skinny<<<dim3(1, MTOT/64), 256>>>(pXIH, pXIL, pW1TH, pW1TL, pXX1,
                                                 MTOT, CDIM);
    /* X = x_in @ value_w^T */
    gemm_wmma3<<<dim3(CDIM/128, MTOT/128), 256>>>(pXIH, pXIL, pVWH, pVWL, pX,
                                                  MTOT, CDIM, CDIM);
    /* XH/XL = split(X) */
    split_kernel<<<SPLIT_BLK_X, 256>>>(pX, pXH, pXL, (int)(SZ / 4));
    /* XW1 = tanh(X @ w_w1)  (N=32 wmma) */
    gemm_wmma3_n32<<<dim3(1, MTOT/64), 256>>>(pXH, pXL, pWW1TH, pWW1TL, pXW1,
                                              MTOT, CDIM);
    /* XW = X + dxprev*(time_maa_w + XW1 @ w_w2) -> bf16 hi/lo (epi=3) */
    gemm_nn<<<dim3(CDIM/128, MTOT/64), 256>>>(pXW1, 32, 0, ww2, CDIM, (float*)0, CDIM,
                                              MTOT, CDIM, 32, 3, NUL,
                                              pX, shiftst, tmw, pXWH, pXWL, NUL);
    /* T1 = tanh(XW @ decay_w1)  (skinny wmma) */
    gemm_wmma3_skinny<<<dim3(1, MTOT/64), 256>>>(pXWH, pXWL, pDW1TH, pDW1TL, pT1,
                                                 MTOT, CDIM);
    /* DEC = exp(-exp(time_decay + T1 @ decay_w2)) */
    gemm_nn<<<dim3(CDIM/128, MTOT/64), 256>>>(pT1, 128, 0, dw2, CDIM, pDEC, CDIM,
                                              MTOT, CDIM, 128, 2, tdecay, NUL, NUL, NUL, NB, NB, NUL);
    /* fused MIX GEMM + rkvv epilogues */
    gemm_nn<<<dim3(CDIM/128, MTOT/64), 256>>>(pXX1, 128, 0, maa_w2, CDIM, pR, CDIM,
                                              MTOT, CDIM, 32, 5, tmr,
                                              pX, shiftst, trec, NB, NB, NUL);
    gemm_nn<<<dim3(CDIM/128, MTOT/64), 256>>>(pXX1, 128, 32, maa_w2 + (size_t)32*CDIM, CDIM, pK, CDIM,
                                              MTOT, CDIM, 32, 6, tmk,
                                              pX, shiftst, tkey, NB, NB, pDEC);
    gemm_nn<<<dim3(CDIM/128, MTOT/64), 256>>>(pXX1, 128, 64, maa_w2 + (size_t)64*CDIM, CDIM, pV, CDIM,
                                              MTOT, CDIM, 32, 4, tmv,
                                              pX, shiftst, NUL, NB, NB, NUL);
    gemm_nn<<<dim3(CDIM/128, MTOT/64), 256>>>(pXX1, 128, 96, maa_w2 + (size_t)96*CDIM, CDIM, pV2, CDIM,
                                              MTOT, CDIM, 32, 4, tmv2,
                                              pX, shiftst, NUL, NB, NB, NUL);
    /* WKV scan (8-step groups) */
    wkv_kernel<<<BATCH*NH, 256>>>(pR, pK, pV, pDEC, wkvstate, pY);
    /* yn = LN(y + v2) -> bf16 hi/lo */
    ln_kernel<<<MTOT, 256>>>(pY, pV2, gamma, beta, pYH, pYL);
    /* out = yn @ output_w^T */
    gemm_wmma3<<<dim3(CDIM/128, MTOT/128), 256>>>(pYH, pYL, pOWH, pOWL, out,
                                                  MTOT, CDIM, CDIM);
}